// round 1
// baseline (speedup 1.0000x reference)
#include <cuda_runtime.h>
#include <math.h>

// Problem constants
#define BB   4
#define LL   8192
#define DD   1024
#define HH   16
#define DH   64
#define MM   (BB*LL)       // 32768 rows
#define N3D  (3*DD)        // 3072
#define NCHUNK 8
#define CHUNK (LL/NCHUNK)  // 1024
#define NBH  (BB*HH)       // 64

// ---------------- scratch (static device globals; no allocation) ----------------
__device__ float g_qkv[(size_t)MM * N3D];          // 402 MB: phi(q) | phi(k)*m | v*m
__device__ float g_y[(size_t)MM * DD];             // 128 MB
__device__ float g_kv_part[(size_t)NCHUNK * NBH * DH * DH];
__device__ float g_ksum_part[(size_t)NCHUNK * NBH * DH];
__device__ float g_kv[(size_t)NBH * DH * DH];
__device__ float g_ksum[(size_t)NBH * DH];

__device__ __forceinline__ float phi_f(float z) {
    // elu(z)+1 : z>0 -> z+1 ; else exp(z)
    return z > 0.0f ? z + 1.0f : expf(z);
}

// ---------------- SGEMM 128x128x8, 256 threads, 8x8/thread ----------------
// A [M,K] row-major, B [K,N] row-major, C [M,N] row-major.
// EPI==1: qkv epilogue (phi / phi*mask / *mask by column region)
// EPI==2: *mask epilogue
template<int EPI>
__global__ __launch_bounds__(256, 2)
void sgemm128(const float* __restrict__ A, const float* __restrict__ B,
              float* __restrict__ C, int M, int N, int K,
              const int* __restrict__ mask)
{
    const int BM = 128, BN = 128, BK = 8, TM = 8, TN = 8;
    __shared__ float As[BK][BM];   // transposed A tile
    __shared__ float Bs[BK][BN];

    const int tid  = threadIdx.x;
    const int brow = blockIdx.y;
    const int bcol = blockIdx.x;

    const float* Ab = A + (size_t)brow * BM * K;
    const float* Bb = B + (size_t)bcol * BN;

    const int arow  = tid >> 1;          // 0..127
    const int acol  = (tid & 1) * 4;     // 0 or 4
    const int browi = tid >> 5;          // 0..7
    const int bcoli = (tid & 31) * 4;    // 0..124

    const int trow = (tid >> 4) * TM;    // 0..120
    const int tcol = (tid & 15) * TN;    // 0..120

    float acc[TM][TN];
    #pragma unroll
    for (int i = 0; i < TM; i++)
        #pragma unroll
        for (int j = 0; j < TN; j++) acc[i][j] = 0.0f;

    for (int k0 = 0; k0 < K; k0 += BK) {
        float4 a4 = *(const float4*)(Ab + (size_t)arow * K + k0 + acol);
        As[acol + 0][arow] = a4.x;
        As[acol + 1][arow] = a4.y;
        As[acol + 2][arow] = a4.z;
        As[acol + 3][arow] = a4.w;

        float4 b4 = *(const float4*)(Bb + (size_t)(k0 + browi) * N + bcoli);
        *(float4*)&Bs[browi][bcoli] = b4;

        __syncthreads();

        #pragma unroll
        for (int kk = 0; kk < BK; kk++) {
            float ra[TM], rb[TN];
            #pragma unroll
            for (int i = 0; i < TM; i++) ra[i] = As[kk][trow + i];
            #pragma unroll
            for (int j = 0; j < TN; j++) rb[j] = Bs[kk][tcol + j];
            #pragma unroll
            for (int i = 0; i < TM; i++)
                #pragma unroll
                for (int j = 0; j < TN; j++)
                    acc[i][j] += ra[i] * rb[j];
        }
        __syncthreads();
    }

    // column-region for EPI==1 (each 128-wide tile lies entirely in one region)
    const int region = (bcol * BN) / DD;   // 0=q, 1=k, 2=v

    #pragma unroll
    for (int i = 0; i < TM; i++) {
        const int row = brow * BM + trow + i;
        float mval = 1.0f;
        if (EPI > 0) mval = (float)mask[row];
        float* crow = C + (size_t)row * N + bcol * BN + tcol;
        #pragma unroll
        for (int j = 0; j < TN; j += 4) {
            float4 o;
            float v0 = acc[i][j + 0], v1 = acc[i][j + 1];
            float v2 = acc[i][j + 2], v3 = acc[i][j + 3];
            if (EPI == 1) {
                if (region == 0) {
                    v0 = phi_f(v0); v1 = phi_f(v1); v2 = phi_f(v2); v3 = phi_f(v3);
                } else if (region == 1) {
                    v0 = phi_f(v0) * mval; v1 = phi_f(v1) * mval;
                    v2 = phi_f(v2) * mval; v3 = phi_f(v3) * mval;
                } else {
                    v0 *= mval; v1 *= mval; v2 *= mval; v3 *= mval;
                }
            } else if (EPI == 2) {
                v0 *= mval; v1 *= mval; v2 *= mval; v3 *= mval;
            }
            o.x = v0; o.y = v1; o.z = v2; o.w = v3;
            *(float4*)(crow + j) = o;
        }
    }
}

// ---------------- Stage 2: kv / ksum partials over L chunks ----------------
// grid: (NBH, NCHUNK), 256 threads (16x16), 4x4 tile each of the 64x64 kv.
__global__ __launch_bounds__(256)
void kv_partial_kernel()
{
    const int bh    = blockIdx.x;   // 0..63
    const int chunk = blockIdx.y;   // 0..7
    const int b = bh / HH, h = bh % HH;
    const int tid = threadIdx.x;
    const int ty = tid >> 4, tx = tid & 15;

    __shared__ float ks[8][DH];
    __shared__ float vs[8][DH];

    float acc[4][4];
    #pragma unroll
    for (int i = 0; i < 4; i++)
        #pragma unroll
        for (int j = 0; j < 4; j++) acc[i][j] = 0.0f;
    float ksacc[4] = {0.f, 0.f, 0.f, 0.f};

    const size_t rowbase = (size_t)b * LL + (size_t)chunk * CHUNK;
    const float* kptr = g_qkv + rowbase * N3D + DD     + h * DH;
    const float* vptr = g_qkv + rowbase * N3D + 2 * DD + h * DH;

    const int lr  = (tid & 127) >> 4;    // 0..7
    const int lc4 = (tid & 15) * 4;      // 0..60

    for (int l0 = 0; l0 < CHUNK; l0 += 8) {
        const float* src = (tid < 128) ? kptr : vptr;
        float4 d4 = *(const float4*)(src + (size_t)(l0 + lr) * N3D + lc4);
        if (tid < 128) *(float4*)&ks[lr][lc4] = d4;
        else           *(float4*)&vs[lr][lc4] = d4;
        __syncthreads();

        #pragma unroll
        for (int r = 0; r < 8; r++) {
            float kr[4], vr[4];
            #pragma unroll
            for (int i = 0; i < 4; i++) kr[i] = ks[r][ty * 4 + i];
            #pragma unroll
            for (int j = 0; j < 4; j++) vr[j] = vs[r][tx * 4 + j];
            #pragma unroll
            for (int i = 0; i < 4; i++)
                #pragma unroll
                for (int j = 0; j < 4; j++)
                    acc[i][j] += kr[i] * vr[j];
            if (tx == 0) {
                #pragma unroll
                for (int i = 0; i < 4; i++) ksacc[i] += kr[i];
            }
        }
        __syncthreads();
    }

    float* out = g_kv_part + ((size_t)chunk * NBH + bh) * DH * DH;
    #pragma unroll
    for (int i = 0; i < 4; i++)
        #pragma unroll
        for (int j = 0; j < 4; j++)
            out[(ty * 4 + i) * DH + tx * 4 + j] = acc[i][j];

    if (tx == 0) {
        float* ko = g_ksum_part + ((size_t)chunk * NBH + bh) * DH;
        #pragma unroll
        for (int i = 0; i < 4; i++) ko[ty * 4 + i] = ksacc[i];
    }
}

// ---------------- Stage 2b: deterministic reduce of partials ----------------
__global__ void kv_final_kernel()
{
    const int bh = blockIdx.x;
    for (int idx = threadIdx.x; idx < DH * DH; idx += blockDim.x) {
        float s = 0.0f;
        #pragma unroll
        for (int c = 0; c < NCHUNK; c++)
            s += g_kv_part[((size_t)c * NBH + bh) * DH * DH + idx];
        g_kv[(size_t)bh * DH * DH + idx] = s;
    }
    for (int idx = threadIdx.x; idx < DH; idx += blockDim.x) {
        float s = 0.0f;
        #pragma unroll
        for (int c = 0; c < NCHUNK; c++)
            s += g_ksum_part[((size_t)c * NBH + bh) * DH + idx];
        g_ksum[(size_t)bh * DH + idx] = s;
    }
}

// ---------------- Stage 3: y = (q @ kv) * z ----------------
// grid: (L/64, NBH); block 256. 64 rows x 64 cols per block; 4 threads/row, 16 cols each.
__global__ __launch_bounds__(256)
void apply_kernel()
{
    const int lt = blockIdx.x;       // 0..127 (tiles of 64 l-rows)
    const int bh = blockIdx.y;       // 0..63
    const int b = bh / HH, h = bh % HH;
    const int tid = threadIdx.x;

    __shared__ float kv_s[DH][DH];
    __shared__ float ks_s[DH];
    __shared__ float q_s[64][DH + 1];

    const float* kvsrc = g_kv + (size_t)bh * DH * DH;
    for (int i = tid; i < DH * DH / 4; i += 256) {
        float4 v4 = *(const float4*)(kvsrc + (size_t)i * 4);
        int d = (i * 4) / DH, m = (i * 4) % DH;
        *(float4*)&kv_s[d][m] = v4;
    }
    if (tid < DH) ks_s[tid] = g_ksum[(size_t)bh * DH + tid];

    const size_t rowbase = (size_t)b * LL + (size_t)lt * 64;
    const float* qsrc = g_qkv + rowbase * N3D + h * DH;
    for (int i = tid; i < 64 * DH / 4; i += 256) {
        int r = (i * 4) / DH, c = (i * 4) % DH;
        float4 v4 = *(const float4*)(qsrc + (size_t)r * N3D + c);
        q_s[r][c + 0] = v4.x; q_s[r][c + 1] = v4.y;
        q_s[r][c + 2] = v4.z; q_s[r][c + 3] = v4.w;
    }
    __syncthreads();

    const int r   = tid >> 2;        // 0..63
    const int sub = tid & 3;         // 0..3
    const int m0  = sub * 16;

    float acc[16];
    #pragma unroll
    for (int j = 0; j < 16; j++) acc[j] = 0.0f;
    float dot = 0.0f;

    #pragma unroll 4
    for (int d = 0; d < DH; d++) {
        float qv = q_s[r][d];
        dot += qv * ks_s[d];
        float4 k0 = *(const float4*)&kv_s[d][m0 + 0];
        float4 k1 = *(const float4*)&kv_s[d][m0 + 4];
        float4 k2 = *(const float4*)&kv_s[d][m0 + 8];
        float4 k3 = *(const float4*)&kv_s[d][m0 + 12];
        acc[0]  += qv * k0.x; acc[1]  += qv * k0.y; acc[2]  += qv * k0.z; acc[3]  += qv * k0.w;
        acc[4]  += qv * k1.x; acc[5]  += qv * k1.y; acc[6]  += qv * k1.z; acc[7]  += qv * k1.w;
        acc[8]  += qv * k2.x; acc[9]  += qv * k2.y; acc[10] += qv * k2.z; acc[11] += qv * k2.w;
        acc[12] += qv * k3.x; acc[13] += qv * k3.y; acc[14] += qv * k3.z; acc[15] += qv * k3.w;
    }

    const float z = 1.0f / (dot + 1e-6f);
    float* yout = g_y + (rowbase + r) * (size_t)DD + h * DH + m0;
    #pragma unroll
    for (int j = 0; j < 16; j += 4) {
        float4 o;
        o.x = acc[j + 0] * z; o.y = acc[j + 1] * z;
        o.z = acc[j + 2] * z; o.w = acc[j + 3] * z;
        *(float4*)(yout + j) = o;
    }
}

// ---------------- launch ----------------
extern "C" void kernel_launch(void* const* d_in, const int* in_sizes, int n_in,
                              void* d_out, int out_size)
{
    (void)in_sizes; (void)n_in; (void)out_size;
    const float* x    = (const float*)d_in[0];
    const int*   mask = (const int*)  d_in[1];
    const float* Wqkv = (const float*)d_in[2];
    const float* Wout = (const float*)d_in[3];
    float* out = (float*)d_out;

    float *qkv_p = nullptr, *y_p = nullptr;
    cudaGetSymbolAddress((void**)&qkv_p, g_qkv);
    cudaGetSymbolAddress((void**)&y_p,   g_y);

    // G1: qkv = x @ Wqkv with phi/mask epilogue
    {
        dim3 grid(N3D / 128, MM / 128);
        sgemm128<1><<<grid, 256>>>(x, Wqkv, qkv_p, MM, N3D, DD, mask);
    }
    // S2: kv/ksum partials + deterministic reduce
    kv_partial_kernel<<<dim3(NBH, NCHUNK), 256>>>();
    kv_final_kernel<<<NBH, 256>>>();
    // S3: y = (q @ kv) * z
    apply_kernel<<<dim3(LL / 64, NBH), 256>>>();
    // G2: out = (y @ Wout) * mask
    {
        dim3 grid(DD / 128, MM / 128);
        sgemm128<2><<<grid, 256>>>(y_p, Wout, out, MM, DD, DD, mask);
    }
}

// round 3
// speedup vs baseline: 2.1268x; 2.1268x over previous
#include <cuda_runtime.h>
#include <cuda_bf16.h>
#include <cstdint>
#include <math.h>

// ---------------- problem constants ----------------
#define BB   4
#define LL   8192
#define DD   1024
#define HH   16
#define DH   64
#define MM   (BB*LL)       // 32768
#define N3D  (3*DD)        // 3072
#define NCHUNK 8
#define CHUNK (LL/NCHUNK)  // 1024
#define NBH  (BB*HH)       // 64

// ---------------- scratch ----------------
__device__ float g_qkv[(size_t)MM * N3D];                                    // phi(q) | phi(k)*m | v*m
__device__ __nv_bfloat16 g_xhi[(size_t)MM * DD], g_xlo[(size_t)MM * DD];
__device__ __nv_bfloat16 g_whi[(size_t)N3D * DD], g_wlo[(size_t)N3D * DD];   // Wqkv^T [N,K]
__device__ __nv_bfloat16 g_yhi[(size_t)MM * DD], g_ylo[(size_t)MM * DD];
__device__ __nv_bfloat16 g_wohi[(size_t)DD * DD], g_wolo[(size_t)DD * DD];   // Wout^T [N,K]
__device__ float g_kv_part[(size_t)NCHUNK * NBH * DH * DH];
__device__ float g_ksum_part[(size_t)NCHUNK * NBH * DH];
__device__ float g_kv[(size_t)NBH * DH * DH];
__device__ float g_ksum[(size_t)NBH * DH];

// ---------------- helpers ----------------
__device__ __forceinline__ uint32_t smem_u32(const void* p) {
    uint32_t a;
    asm("{ .reg .u64 t; cvta.to.shared.u64 t, %1; cvt.u32.u64 %0, t; }" : "=r"(a) : "l"(p));
    return a;
}
#define CP_ASYNC16(sa, ga) asm volatile("cp.async.cg.shared.global [%0], [%1], 16;" :: "r"(sa), "l"(ga))
#define CP_COMMIT()        asm volatile("cp.async.commit_group;" ::: "memory")
#define CP_WAIT(n)         asm volatile("cp.async.wait_group %0;" :: "n"(n) : "memory")

#define LDMX4(r0, r1, r2, r3, a) \
    asm volatile("ldmatrix.sync.aligned.m8n8.x4.shared.b16 {%0,%1,%2,%3}, [%4];" \
        : "=r"(r0), "=r"(r1), "=r"(r2), "=r"(r3) : "r"(a))

#define MMA16816(c, a, b0, b1) \
    asm volatile("mma.sync.aligned.m16n8k16.row.col.f32.bf16.bf16.f32 " \
        "{%0,%1,%2,%3}, {%4,%5,%6,%7}, {%8,%9}, {%0,%1,%2,%3};" \
        : "+f"((c)[0]), "+f"((c)[1]), "+f"((c)[2]), "+f"((c)[3]) \
        : "r"((a)[0]), "r"((a)[1]), "r"((a)[2]), "r"((a)[3]), "r"(b0), "r"(b1))

__device__ __forceinline__ float phi_f(float z) { return z > 0.0f ? z + 1.0f : expf(z); }

// ---------------- split conversion kernels ----------------
__global__ void conv_split(const float* __restrict__ in, __nv_bfloat16* __restrict__ hi,
                           __nv_bfloat16* __restrict__ lo, int n4)
{
    int i = blockIdx.x * 256 + threadIdx.x;
    if (i >= n4) return;
    float4 v = ((const float4*)in)[i];
    float f[4] = {v.x, v.y, v.z, v.w};
    union { __nv_bfloat16 b[4]; uint2 u; } H, L;
    #pragma unroll
    for (int j = 0; j < 4; j++) {
        __nv_bfloat16 h = __float2bfloat16(f[j]);
        H.b[j] = h;
        L.b[j] = __float2bfloat16(f[j] - __bfloat162float(h));
    }
    ((uint2*)hi)[i] = H.u;
    ((uint2*)lo)[i] = L.u;
}

// W [R,C] row-major -> out [C,R] bf16 hi/lo
__global__ void conv_wT(const float* __restrict__ W, __nv_bfloat16* __restrict__ hi,
                        __nv_bfloat16* __restrict__ lo, int R, int Ccols)
{
    __shared__ float t[32][33];
    int cx = blockIdx.x * 32, rx = blockIdx.y * 32;
    for (int i = threadIdx.y; i < 32; i += 8)
        t[i][threadIdx.x] = W[(size_t)(rx + i) * Ccols + cx + threadIdx.x];
    __syncthreads();
    for (int i = threadIdx.y; i < 32; i += 8) {
        float v = t[threadIdx.x][i];
        __nv_bfloat16 h = __float2bfloat16(v);
        size_t o = (size_t)(cx + i) * R + rx + threadIdx.x;
        hi[o] = h;
        lo[o] = __float2bfloat16(v - __bfloat162float(h));
    }
}

// ---------------- mma.sync split-bf16 GEMM ----------------
// C[M,N] = Ahi*Bhi + Ahi*Blo + Alo*Bhi ; A [M,K] K-major, B [N,K] K-major, K=1024.
// Tile 128x128, BK=32, 8 warps (4 m x 2 n), warp tile 32x64, 3-stage cp.async pipeline.
// Smem tile rows padded to 80B (conflict-free ldmatrix, no swizzle).
#define ROWB 80
#define TILE_B (128 * ROWB)            // 10240 per matrix
#define STAGE_B (2 * TILE_B)           // 20480
#define SMEM_GEMM (3 * STAGE_B)        // 61440
#define KSTEPS 32                      // per pass (K=1024, BK=32)
#define NSTEP  (3 * KSTEPS)            // 96

__device__ __forceinline__ void g_load(uint32_t sbuf,
    const __nv_bfloat16* __restrict__ A, const __nv_bfloat16* __restrict__ B,
    int m0, int n0, int K, int kk, int tid)
{
    #pragma unroll
    for (int i = 0; i < 2; i++) {
        int id = tid + i * 256;
        int row = id >> 2, ch = id & 3;
        uint32_t so = (uint32_t)(row * ROWB + ch * 16);
        CP_ASYNC16(sbuf + so,          (const char*)(A + (size_t)(m0 + row) * K + kk + ch * 8));
        CP_ASYNC16(sbuf + TILE_B + so, (const char*)(B + (size_t)(n0 + row) * K + kk + ch * 8));
    }
}

template<int EPI>
__global__ __launch_bounds__(256)
void gemm_bf16_split(const __nv_bfloat16* __restrict__ Ahi, const __nv_bfloat16* __restrict__ Alo,
                     const __nv_bfloat16* __restrict__ Bhi, const __nv_bfloat16* __restrict__ Blo,
                     float* __restrict__ C, int N, int K, const int* __restrict__ mask)
{
    extern __shared__ char smem[];
    const uint32_t sb = smem_u32(smem);
    const int tid = threadIdx.x;
    const int wid = tid >> 5, lane = tid & 31;
    const int wm = wid & 3, wn = wid >> 2;
    const int m0 = blockIdx.y * 128, n0 = blockIdx.x * 128;

    float acc[2][8][4];
    #pragma unroll
    for (int mi = 0; mi < 2; mi++)
        #pragma unroll
        for (int j = 0; j < 8; j++)
            #pragma unroll
            for (int e = 0; e < 4; e++) acc[mi][j][e] = 0.0f;

    // ldmatrix lane addresses (byte offsets within tile)
    const uint32_t a_off = (uint32_t)((wm * 32 + (lane & 15)) * ROWB + (lane >> 4) * 16);
    const uint32_t b_off = (uint32_t)((wn * 64 + ((lane >> 4) & 1) * 8 + (lane & 7)) * ROWB
                                      + ((lane >> 3) & 1) * 16);

    // prologue
    {
        g_load(sb, Ahi, Bhi, m0, n0, K, 0, tid);  CP_COMMIT();
        g_load(sb + STAGE_B, Ahi, Bhi, m0, n0, K, 32, tid);  CP_COMMIT();
    }

    for (int s = 0; s < NSTEP; s++) {
        if (s + 2 < NSTEP) CP_WAIT(1); else CP_WAIT(0);
        __syncthreads();
        if (s + 2 < NSTEP) {
            const int s2 = s + 2;
            const int pass = s2 >> 5;
            const __nv_bfloat16* A = (pass == 2) ? Alo : Ahi;
            const __nv_bfloat16* B = (pass == 1) ? Blo : Bhi;
            g_load(sb + (s2 % 3) * STAGE_B, A, B, m0, n0, K, (s2 & 31) * 32, tid);
            CP_COMMIT();
        }
        const uint32_t stage = sb + (s % 3) * STAGE_B;
        const uint32_t sA = stage + a_off;
        const uint32_t sB = stage + TILE_B + b_off;
        #pragma unroll
        for (int c = 0; c < 2; c++) {       // two k16 per BK=32
            uint32_t a[2][4];
            LDMX4(a[0][0], a[0][1], a[0][2], a[0][3], sA + c * 32);
            LDMX4(a[1][0], a[1][1], a[1][2], a[1][3], sA + 16 * ROWB + c * 32);
            uint32_t b[4][4];
            #pragma unroll
            for (int jp = 0; jp < 4; jp++)
                LDMX4(b[jp][0], b[jp][1], b[jp][2], b[jp][3], sB + jp * (16 * ROWB) + c * 32);
            #pragma unroll
            for (int mi = 0; mi < 2; mi++)
                #pragma unroll
                for (int j = 0; j < 8; j++) {
                    const uint32_t* bp = b[j >> 1];
                    if (j & 1) MMA16816(acc[mi][j], a[mi], bp[2], bp[3]);
                    else       MMA16816(acc[mi][j], a[mi], bp[0], bp[1]);
                }
        }
    }

    // epilogue
    const int gr = lane >> 2, tc = lane & 3;
    const int region = n0 >> 10;   // 0=q, 1=k, 2=v (EPI==1)
    #pragma unroll
    for (int mi = 0; mi < 2; mi++) {
        const int rbase = m0 + wm * 32 + mi * 16 + gr;
        float mv0 = 1.0f, mv1 = 1.0f;
        if (EPI > 0) { mv0 = (float)mask[rbase]; mv1 = (float)mask[rbase + 8]; }
        #pragma unroll
        for (int j = 0; j < 8; j++) {
            const int col = n0 + wn * 64 + j * 8 + tc * 2;
            float v0 = acc[mi][j][0], v1 = acc[mi][j][1];
            float v2 = acc[mi][j][2], v3 = acc[mi][j][3];
            if (EPI == 1) {
                if (region == 0)      { v0 = phi_f(v0); v1 = phi_f(v1); v2 = phi_f(v2); v3 = phi_f(v3); }
                else if (region == 1) { v0 = phi_f(v0) * mv0; v1 = phi_f(v1) * mv0;
                                        v2 = phi_f(v2) * mv1; v3 = phi_f(v3) * mv1; }
                else                  { v0 *= mv0; v1 *= mv0; v2 *= mv1; v3 *= mv1; }
            } else if (EPI == 2) { v0 *= mv0; v1 *= mv0; v2 *= mv1; v3 *= mv1; }
            float2 p0 = make_float2(v0, v1), p1 = make_float2(v2, v3);
            *(float2*)(C + (size_t)rbase * N + col)       = p0;
            *(float2*)(C + (size_t)(rbase + 8) * N + col) = p1;
        }
    }
}

// ---------------- Stage 2: kv / ksum partials ----------------
__global__ __launch_bounds__(256)
void kv_partial_kernel()
{
    const int bh = blockIdx.x, chunk = blockIdx.y;
    const int b = bh / HH, h = bh % HH;
    const int tid = threadIdx.x;
    const int ty = tid >> 4, tx = tid & 15;

    __shared__ float ks[8][DH];
    __shared__ float vs[8][DH];

    float acc[4][4];
    #pragma unroll
    for (int i = 0; i < 4; i++)
        #pragma unroll
        for (int j = 0; j < 4; j++) acc[i][j] = 0.0f;
    float ksacc[4] = {0.f, 0.f, 0.f, 0.f};

    const size_t rowbase = (size_t)b * LL + (size_t)chunk * CHUNK;
    const float* kptr = g_qkv + rowbase * N3D + DD     + h * DH;
    const float* vptr = g_qkv + rowbase * N3D + 2 * DD + h * DH;

    const int lr  = (tid & 127) >> 4;
    const int lc4 = (tid & 15) * 4;

    for (int l0 = 0; l0 < CHUNK; l0 += 8) {
        const float* src = (tid < 128) ? kptr : vptr;
        float4 d4 = *(const float4*)(src + (size_t)(l0 + lr) * N3D + lc4);
        if (tid < 128) *(float4*)&ks[lr][lc4] = d4;
        else           *(float4*)&vs[lr][lc4] = d4;
        __syncthreads();

        #pragma unroll
        for (int r = 0; r < 8; r++) {
            float kr[4], vr[4];
            #pragma unroll
            for (int i = 0; i < 4; i++) kr[i] = ks[r][ty * 4 + i];
            #pragma unroll
            for (int j = 0; j < 4; j++) vr[j] = vs[r][tx * 4 + j];
            #pragma unroll
            for (int i = 0; i < 4; i++)
                #pragma unroll
                for (int j = 0; j < 4; j++)
                    acc[i][j] += kr[i] * vr[j];
            if (tx == 0) {
                #pragma unroll
                for (int i = 0; i < 4; i++) ksacc[i] += kr[i];
            }
        }
        __syncthreads();
    }

    float* out = g_kv_part + ((size_t)chunk * NBH + bh) * DH * DH;
    #pragma unroll
    for (int i = 0; i < 4; i++)
        #pragma unroll
        for (int j = 0; j < 4; j++)
            out[(ty * 4 + i) * DH + tx * 4 + j] = acc[i][j];
    if (tx == 0) {
        float* ko = g_ksum_part + ((size_t)chunk * NBH + bh) * DH;
        #pragma unroll
        for (int i = 0; i < 4; i++) ko[ty * 4 + i] = ksacc[i];
    }
}

__global__ void kv_final_kernel()
{
    const int bh = blockIdx.x;
    for (int idx = threadIdx.x; idx < DH * DH; idx += blockDim.x) {
        float s = 0.0f;
        #pragma unroll
        for (int c = 0; c < NCHUNK; c++)
            s += g_kv_part[((size_t)c * NBH + bh) * DH * DH + idx];
        g_kv[(size_t)bh * DH * DH + idx] = s;
    }
    for (int idx = threadIdx.x; idx < DH; idx += blockDim.x) {
        float s = 0.0f;
        #pragma unroll
        for (int c = 0; c < NCHUNK; c++)
            s += g_ksum_part[((size_t)c * NBH + bh) * DH + idx];
        g_ksum[(size_t)bh * DH + idx] = s;
    }
}

// ---------------- Stage 3: y = (q @ kv) * z -> bf16 hi/lo ----------------
#define SMEM_APPLY ((4096 + 64 + 256 * 65) * 4)   // 83200 bytes

__global__ __launch_bounds__(256)
void apply_kernel2()
{
    extern __shared__ float sm[];
    float* kv_s = sm;
    float* ks_s = sm + 4096;
    float* q_s  = sm + 4096 + 64;   // [256][65]

    const int lt = blockIdx.x, bh = blockIdx.y;
    const int b = bh >> 4, head = bh & 15;
    const int tid = threadIdx.x;

    const float* kvsrc = g_kv + (size_t)bh * DH * DH;
    for (int i = tid; i < DH * DH / 4; i += 256)
        ((float4*)kv_s)[i] = ((const float4*)kvsrc)[i];
    if (tid < DH) ks_s[tid] = g_ksum[(size_t)bh * DH + tid];

    const size_t rowbase = (size_t)b * LL + (size_t)lt * 256;
    const float* qsrc = g_qkv + rowbase * N3D + head * DH;
    for (int i = tid; i < 256 * 16; i += 256) {
        int r = i >> 4, c = (i & 15) * 4;
        float4 v = *(const float4*)(qsrc + (size_t)r * N3D + c);
        float* qd = q_s + r * 65 + c;
        qd[0] = v.x; qd[1] = v.y; qd[2] = v.z; qd[3] = v.w;
    }
    __syncthreads();

    const int rt = tid >> 2, ct = tid & 3;
    const int r0 = rt * 4, c0 = ct * 16;

    float acc[4][16];
    #pragma unroll
    for (int i = 0; i < 4; i++)
        #pragma unroll
        for (int j = 0; j < 16; j++) acc[i][j] = 0.0f;
    float dot[4] = {0.f, 0.f, 0.f, 0.f};

    for (int d = 0; d < DH; d++) {
        float kvv[16];
        #pragma unroll
        for (int j = 0; j < 16; j += 4)
            *(float4*)&kvv[j] = *(const float4*)&kv_s[d * 64 + c0 + j];
        const float kss = ks_s[d];
        #pragma unroll
        for (int i = 0; i < 4; i++) {
            float qv = q_s[(r0 + i) * 65 + d];
            dot[i] += qv * kss;
            #pragma unroll
            for (int j = 0; j < 16; j++) acc[i][j] += qv * kvv[j];
        }
    }

    #pragma unroll
    for (int i = 0; i < 4; i++) {
        const float z = 1.0f / (dot[i] + 1e-6f);
        const size_t row = rowbase + r0 + i;
        union { __nv_bfloat16 b[8]; uint4 u; } H0, H1, L0, L1;
        #pragma unroll
        for (int j = 0; j < 16; j++) {
            float v = acc[i][j] * z;
            __nv_bfloat16 h = __float2bfloat16(v);
            __nv_bfloat16 l = __float2bfloat16(v - __bfloat162float(h));
            if (j < 8) { H0.b[j] = h; L0.b[j] = l; }
            else       { H1.b[j - 8] = h; L1.b[j - 8] = l; }
        }
        const size_t o = row * DD + head * DH + c0;
        *(uint4*)(g_yhi + o)     = H0.u;
        *(uint4*)(g_yhi + o + 8) = H1.u;
        *(uint4*)(g_ylo + o)     = L0.u;
        *(uint4*)(g_ylo + o + 8) = L1.u;
    }
}

// ---------------- launch ----------------
extern "C" void kernel_launch(void* const* d_in, const int* in_sizes, int n_in,
                              void* d_out, int out_size)
{
    (void)in_sizes; (void)n_in; (void)out_size;
    const float* x    = (const float*)d_in[0];
    const int*   mask = (const int*)  d_in[1];
    const float* Wqkv = (const float*)d_in[2];
    const float* Wout = (const float*)d_in[3];
    float* out = (float*)d_out;

    __nv_bfloat16 *xhi, *xlo, *whi, *wlo, *yhi, *ylo, *wohi, *wolo;
    float *qkv_p;
    cudaGetSymbolAddress((void**)&xhi,  g_xhi);
    cudaGetSymbolAddress((void**)&xlo,  g_xlo);
    cudaGetSymbolAddress((void**)&whi,  g_whi);
    cudaGetSymbolAddress((void**)&wlo,  g_wlo);
    cudaGetSymbolAddress((void**)&yhi,  g_yhi);
    cudaGetSymbolAddress((void**)&ylo,  g_ylo);
    cudaGetSymbolAddress((void**)&wohi, g_wohi);
    cudaGetSymbolAddress((void**)&wolo, g_wolo);
    cudaGetSymbolAddress((void**)&qkv_p, g_qkv);

    cudaFuncSetAttribute(gemm_bf16_split<1>, cudaFuncAttributeMaxDynamicSharedMemorySize, SMEM_GEMM);
    cudaFuncSetAttribute(gemm_bf16_split<2>, cudaFuncAttributeMaxDynamicSharedMemorySize, SMEM_GEMM);
    cudaFuncSetAttribute(apply_kernel2,      cudaFuncAttributeMaxDynamicSharedMemorySize, SMEM_APPLY);

    // split inputs
    conv_split<<<(MM * DD / 4 + 255) / 256, 256>>>(x, xhi, xlo, MM * DD / 4);
    conv_wT<<<dim3(N3D / 32, DD / 32), dim3(32, 8)>>>(Wqkv, whi, wlo, DD, N3D);
    conv_wT<<<dim3(DD / 32, DD / 32), dim3(32, 8)>>>(Wout, wohi, wolo, DD, DD);

    // G1: qkv = x @ Wqkv (split-bf16 mma.sync) with phi/mask epilogue
    gemm_bf16_split<1><<<dim3(N3D / 128, MM / 128), 256, SMEM_GEMM>>>(
        xhi, xlo, whi, wlo, qkv_p, N3D, DD, mask);

    // S2: kv/ksum
    kv_partial_kernel<<<dim3(NBH, NCHUNK), 256>>>();
    kv_final_kernel<<<NBH, 256>>>();

    // S3: y = (q @ kv) * z  -> bf16 hi/lo
    apply_kernel2<<<dim3(LL / 256, NBH), 256, SMEM_APPLY>>>();

    // G2: out = (y @ Wout) * mask
    gemm_bf16_split<2><<<dim3(DD / 128, MM / 128), 256, SMEM_GEMM>>>(
        yhi, ylo, wohi, wolo, out, DD, DD, mask);
}

// round 5
// speedup vs baseline: 2.6057x; 1.2252x over previous
#include <cuda_runtime.h>
#include <cuda_bf16.h>
#include <cstdint>
#include <math.h>

// ---------------- problem constants ----------------
#define BB   4
#define LL   8192
#define DD   1024
#define HH   16
#define DH   64
#define MM   (BB*LL)       // 32768
#define N3D  (3*DD)        // 3072
#define NCHUNK 8
#define CHUNK (LL/NCHUNK)  // 1024
#define NBH  (BB*HH)       // 64

// ---------------- scratch ----------------
__device__ float g_qkv[(size_t)MM * N3D];                                    // phi(q) | phi(k)*m | v*m
__device__ __nv_bfloat16 g_xhi[(size_t)MM * DD], g_xlo[(size_t)MM * DD];
__device__ __nv_bfloat16 g_whi[(size_t)N3D * DD], g_wlo[(size_t)N3D * DD];   // Wqkv^T [N,K]
__device__ __nv_bfloat16 g_yhi[(size_t)MM * DD], g_ylo[(size_t)MM * DD];
__device__ __nv_bfloat16 g_wohi[(size_t)DD * DD], g_wolo[(size_t)DD * DD];   // Wout^T [N,K]
__device__ float g_kv_part[(size_t)NCHUNK * NBH * DH * DH];
__device__ float g_ksum_part[(size_t)NCHUNK * NBH * DH];
__device__ float g_kv[(size_t)NBH * DH * DH];
__device__ float g_ksum[(size_t)NBH * DH];

// ---------------- helpers ----------------
__device__ __forceinline__ uint32_t smem_u32(const void* p) {
    uint32_t a;
    asm("{ .reg .u64 t; cvta.to.shared.u64 t, %1; cvt.u32.u64 %0, t; }" : "=r"(a) : "l"(p));
    return a;
}
#define CP_ASYNC16(sa, ga) asm volatile("cp.async.cg.shared.global [%0], [%1], 16;" :: "r"(sa), "l"(ga))
#define CP_COMMIT()        asm volatile("cp.async.commit_group;" ::: "memory")
#define CP_WAIT(n)         asm volatile("cp.async.wait_group %0;" :: "n"(n) : "memory")

#define LDMX4(r0, r1, r2, r3, a) \
    asm volatile("ldmatrix.sync.aligned.m8n8.x4.shared.b16 {%0,%1,%2,%3}, [%4];" \
        : "=r"(r0), "=r"(r1), "=r"(r2), "=r"(r3) : "r"(a))

#define MMA16816(c, a, b0, b1) \
    asm volatile("mma.sync.aligned.m16n8k16.row.col.f32.bf16.bf16.f32 " \
        "{%0,%1,%2,%3}, {%4,%5,%6,%7}, {%8,%9}, {%0,%1,%2,%3};" \
        : "+f"((c)[0]), "+f"((c)[1]), "+f"((c)[2]), "+f"((c)[3]) \
        : "r"((a)[0]), "r"((a)[1]), "r"((a)[2]), "r"((a)[3]), "r"(b0), "r"(b1))

__device__ __forceinline__ float phi_f(float z) { return z > 0.0f ? z + 1.0f : expf(z); }

// ---------------- split conversion kernels ----------------
__global__ void conv_split(const float* __restrict__ in, __nv_bfloat16* __restrict__ hi,
                           __nv_bfloat16* __restrict__ lo, int n4)
{
    int i = blockIdx.x * 256 + threadIdx.x;
    if (i >= n4) return;
    float4 v = ((const float4*)in)[i];
    float f[4] = {v.x, v.y, v.z, v.w};
    union { __nv_bfloat16 b[4]; uint2 u; } H, L;
    #pragma unroll
    for (int j = 0; j < 4; j++) {
        __nv_bfloat16 h = __float2bfloat16(f[j]);
        H.b[j] = h;
        L.b[j] = __float2bfloat16(f[j] - __bfloat162float(h));
    }
    ((uint2*)hi)[i] = H.u;
    ((uint2*)lo)[i] = L.u;
}

// W [R,C] row-major -> out [C,R] bf16 hi/lo
__global__ void conv_wT(const float* __restrict__ W, __nv_bfloat16* __restrict__ hi,
                        __nv_bfloat16* __restrict__ lo, int R, int Ccols)
{
    __shared__ float t[32][33];
    int cx = blockIdx.x * 32, rx = blockIdx.y * 32;
    for (int i = threadIdx.y; i < 32; i += 8)
        t[i][threadIdx.x] = W[(size_t)(rx + i) * Ccols + cx + threadIdx.x];
    __syncthreads();
    for (int i = threadIdx.y; i < 32; i += 8) {
        float v = t[threadIdx.x][i];
        __nv_bfloat16 h = __float2bfloat16(v);
        size_t o = (size_t)(cx + i) * R + rx + threadIdx.x;
        hi[o] = h;
        lo[o] = __float2bfloat16(v - __bfloat162float(h));
    }
}

// ---------------- mma.sync split-bf16 GEMM (fused 3-product steps) ----------------
// C[M,N] = Ahi*Bhi + Ahi*Blo + Alo*Bhi ; A [M,K] K-major, B [N,K] K-major, K=1024.
// Tile 128x128, BK=32, 8 warps (4m x 2n), warp tile 32x64.
// Each k-step loads Ahi|Alo|Bhi|Blo (40KB) once and issues all 3 products.
// 2-stage cp.async double buffer. Rows padded to 80B (conflict-free ldmatrix).
#define ROWB 80
#define TILE_B (128 * ROWB)            // 10240 per sub-tile
#define STAGE_B (4 * TILE_B)           // 40960 (AH|AL|BH|BL)
#define SMEM_GEMM (2 * STAGE_B)        // 81920
#define KSTEPS 32                      // K=1024, BK=32

__device__ __forceinline__ void g_load4(uint32_t sbuf,
    const __nv_bfloat16* __restrict__ Ahi, const __nv_bfloat16* __restrict__ Alo,
    const __nv_bfloat16* __restrict__ Bhi, const __nv_bfloat16* __restrict__ Blo,
    int m0, int n0, int K, int kk, int tid)
{
    #pragma unroll
    for (int i = 0; i < 2; i++) {
        int id = tid + i * 256;              // 0..511
        int row = id >> 2, ch = id & 3;      // 128 rows x 4 16B-chunks
        uint32_t so = (uint32_t)(row * ROWB + ch * 16);
        size_t ga = (size_t)(m0 + row) * K + kk + ch * 8;
        size_t gb = (size_t)(n0 + row) * K + kk + ch * 8;
        CP_ASYNC16(sbuf + so,              (const char*)(Ahi + ga));
        CP_ASYNC16(sbuf + TILE_B + so,     (const char*)(Alo + ga));
        CP_ASYNC16(sbuf + 2 * TILE_B + so, (const char*)(Bhi + gb));
        CP_ASYNC16(sbuf + 3 * TILE_B + so, (const char*)(Blo + gb));
    }
}

template<int EPI>
__global__ __launch_bounds__(256, 2)
void gemm_bf16_split(const __nv_bfloat16* __restrict__ Ahi, const __nv_bfloat16* __restrict__ Alo,
                     const __nv_bfloat16* __restrict__ Bhi, const __nv_bfloat16* __restrict__ Blo,
                     float* __restrict__ C, int N, int K, const int* __restrict__ mask)
{
    extern __shared__ char smem[];
    const uint32_t sb = smem_u32(smem);
    const int tid = threadIdx.x;
    const int wid = tid >> 5, lane = tid & 31;
    const int wm = wid & 3, wn = wid >> 2;
    const int m0 = blockIdx.y * 128, n0 = blockIdx.x * 128;

    float acc[2][8][4];
    #pragma unroll
    for (int mi = 0; mi < 2; mi++)
        #pragma unroll
        for (int j = 0; j < 8; j++)
            #pragma unroll
            for (int e = 0; e < 4; e++) acc[mi][j][e] = 0.0f;

    const uint32_t a_off = (uint32_t)((wm * 32 + (lane & 15)) * ROWB + (lane >> 4) * 16);
    const uint32_t b_off = (uint32_t)((wn * 64 + ((lane >> 4) & 1) * 8 + (lane & 7)) * ROWB
                                      + ((lane >> 3) & 1) * 16);

    g_load4(sb, Ahi, Alo, Bhi, Blo, m0, n0, K, 0, tid);
    CP_COMMIT();

    for (int s = 0; s < KSTEPS; s++) {
        CP_WAIT(0);
        __syncthreads();
        if (s + 1 < KSTEPS) {
            g_load4(sb + ((s + 1) & 1) * STAGE_B, Ahi, Alo, Bhi, Blo, m0, n0, K, (s + 1) * 32, tid);
            CP_COMMIT();
        }
        const uint32_t st = sb + (s & 1) * STAGE_B;
        #pragma unroll
        for (int c = 0; c < 2; c++) {
            const uint32_t sAH = st + a_off + c * 32;
            const uint32_t sAL = st + TILE_B + a_off + c * 32;
            const uint32_t sBH = st + 2 * TILE_B + b_off + c * 32;
            const uint32_t sBL = st + 3 * TILE_B + b_off + c * 32;

            uint32_t aH[2][4], bH[4][4];
            LDMX4(aH[0][0], aH[0][1], aH[0][2], aH[0][3], sAH);
            LDMX4(aH[1][0], aH[1][1], aH[1][2], aH[1][3], sAH + 16 * ROWB);
            #pragma unroll
            for (int jp = 0; jp < 4; jp++)
                LDMX4(bH[jp][0], bH[jp][1], bH[jp][2], bH[jp][3], sBH + jp * (16 * ROWB));

            // aH * bH
            #pragma unroll
            for (int mi = 0; mi < 2; mi++)
                #pragma unroll
                for (int j = 0; j < 8; j++) {
                    const uint32_t* bp = bH[j >> 1];
                    if (j & 1) MMA16816(acc[mi][j], aH[mi], bp[2], bp[3]);
                    else       MMA16816(acc[mi][j], aH[mi], bp[0], bp[1]);
                }

            // aH * bL (bL loaded now, aH still resident)
            {
                uint32_t bL[4][4];
                #pragma unroll
                for (int jp = 0; jp < 4; jp++)
                    LDMX4(bL[jp][0], bL[jp][1], bL[jp][2], bL[jp][3], sBL + jp * (16 * ROWB));
                #pragma unroll
                for (int mi = 0; mi < 2; mi++)
                    #pragma unroll
                    for (int j = 0; j < 8; j++) {
                        const uint32_t* bp = bL[j >> 1];
                        if (j & 1) MMA16816(acc[mi][j], aH[mi], bp[2], bp[3]);
                        else       MMA16816(acc[mi][j], aH[mi], bp[0], bp[1]);
                    }
            }

            // aL * bH (aL loaded now, bH still resident)
            {
                uint32_t aL[2][4];
                LDMX4(aL[0][0], aL[0][1], aL[0][2], aL[0][3], sAL);
                LDMX4(aL[1][0], aL[1][1], aL[1][2], aL[1][3], sAL + 16 * ROWB);
                #pragma unroll
                for (int mi = 0; mi < 2; mi++)
                    #pragma unroll
                    for (int j = 0; j < 8; j++) {
                        const uint32_t* bp = bH[j >> 1];
                        if (j & 1) MMA16816(acc[mi][j], aL[mi], bp[2], bp[3]);
                        else       MMA16816(acc[mi][j], aL[mi], bp[0], bp[1]);
                    }
            }
        }
    }

    // epilogue
    const int gr = lane >> 2, tc = lane & 3;
    const int region = n0 >> 10;   // 0=q, 1=k, 2=v (EPI==1)
    #pragma unroll
    for (int mi = 0; mi < 2; mi++) {
        const int rbase = m0 + wm * 32 + mi * 16 + gr;
        float mv0 = 1.0f, mv1 = 1.0f;
        if (EPI > 0) { mv0 = (float)mask[rbase]; mv1 = (float)mask[rbase + 8]; }
        #pragma unroll
        for (int j = 0; j < 8; j++) {
            const int col = n0 + wn * 64 + j * 8 + tc * 2;
            float v0 = acc[mi][j][0], v1 = acc[mi][j][1];
            float v2 = acc[mi][j][2], v3 = acc[mi][j][3];
            if (EPI == 1) {
                if (region == 0)      { v0 = phi_f(v0); v1 = phi_f(v1); v2 = phi_f(v2); v3 = phi_f(v3); }
                else if (region == 1) { v0 = phi_f(v0) * mv0; v1 = phi_f(v1) * mv0;
                                        v2 = phi_f(v2) * mv1; v3 = phi_f(v3) * mv1; }
                else                  { v0 *= mv0; v1 *= mv0; v2 *= mv1; v3 *= mv1; }
            } else if (EPI == 2) { v0 *= mv0; v1 *= mv0; v2 *= mv1; v3 *= mv1; }
            float2 p0 = make_float2(v0, v1), p1 = make_float2(v2, v3);
            *(float2*)(C + (size_t)rbase * N + col)       = p0;
            *(float2*)(C + (size_t)(rbase + 8) * N + col) = p1;
        }
    }
}

// ---------------- Stage 2: kv / ksum partials (cp.async double buffered) ----------------
#define KVROWS 32
__global__ __launch_bounds__(256)
void kv_partial_kernel()
{
    const int bh = blockIdx.x, chunk = blockIdx.y;
    const int b = bh / HH, h = bh % HH;
    const int tid = threadIdx.x;
    const int ty = tid >> 4, tx = tid & 15;

    __shared__ float ks[2][KVROWS][DH];   // 2 x 8KB
    __shared__ float vs[2][KVROWS][DH];

    const size_t rowbase = (size_t)b * LL + (size_t)chunk * CHUNK;
    const float* kptr = g_qkv + rowbase * N3D + DD     + h * DH;
    const float* vptr = g_qkv + rowbase * N3D + 2 * DD + h * DH;

    const uint32_t ksb = smem_u32(&ks[0][0][0]);
    const uint32_t vsb = smem_u32(&vs[0][0][0]);

    auto issue = [&](int buf, int l0) {
        #pragma unroll
        for (int i = 0; i < 2; i++) {
            int id  = tid + i * 256;         // 0..511
            int row = id >> 4, ch = id & 15; // 32 rows x 16 chunks(16B)
            uint32_t so = (uint32_t)(buf * KVROWS * DH * 4 + row * DH * 4 + ch * 16);
            CP_ASYNC16(ksb + so, (const char*)(kptr + (size_t)(l0 + row) * N3D + ch * 4));
            CP_ASYNC16(vsb + so, (const char*)(vptr + (size_t)(l0 + row) * N3D + ch * 4));
        }
        CP_COMMIT();
    };

    float acc[4][4];
    #pragma unroll
    for (int i = 0; i < 4; i++)
        #pragma unroll
        for (int j = 0; j < 4; j++) acc[i][j] = 0.0f;
    float ksacc[4] = {0.f, 0.f, 0.f, 0.f};

    issue(0, 0);
    const int NIT = CHUNK / KVROWS;   // 32
    for (int it = 0; it < NIT; it++) {
        CP_WAIT(0);
        __syncthreads();
        if (it + 1 < NIT) issue((it + 1) & 1, (it + 1) * KVROWS);
        const int buf = it & 1;
        #pragma unroll 8
        for (int r = 0; r < KVROWS; r++) {
            float kr[4], vr[4];
            *(float4*)kr = *(const float4*)&ks[buf][r][ty * 4];
            *(float4*)vr = *(const float4*)&vs[buf][r][tx * 4];
            #pragma unroll
            for (int i = 0; i < 4; i++)
                #pragma unroll
                for (int j = 0; j < 4; j++)
                    acc[i][j] += kr[i] * vr[j];
            if (tx == 0) {
                #pragma unroll
                for (int i = 0; i < 4; i++) ksacc[i] += kr[i];
            }
        }
        __syncthreads();
    }

    float* out = g_kv_part + ((size_t)chunk * NBH + bh) * DH * DH;
    #pragma unroll
    for (int i = 0; i < 4; i++)
        #pragma unroll
        for (int j = 0; j < 4; j++)
            out[(ty * 4 + i) * DH + tx * 4 + j] = acc[i][j];
    if (tx == 0) {
        float* ko = g_ksum_part + ((size_t)chunk * NBH + bh) * DH;
        #pragma unroll
        for (int i = 0; i < 4; i++) ko[ty * 4 + i] = ksacc[i];
    }
}

__global__ void kv_final_kernel()
{
    const int bh = blockIdx.x;
    for (int idx = threadIdx.x; idx < DH * DH; idx += blockDim.x) {
        float s = 0.0f;
        #pragma unroll
        for (int c = 0; c < NCHUNK; c++)
            s += g_kv_part[((size_t)c * NBH + bh) * DH * DH + idx];
        g_kv[(size_t)bh * DH * DH + idx] = s;
    }
    for (int idx = threadIdx.x; idx < DH; idx += blockDim.x) {
        float s = 0.0f;
        #pragma unroll
        for (int c = 0; c < NCHUNK; c++)
            s += g_ksum_part[((size_t)c * NBH + bh) * DH + idx];
        g_ksum[(size_t)bh * DH + idx] = s;
    }
}

// ---------------- Stage 3: y = (q @ kv) * z -> bf16 hi/lo ----------------
#define SMEM_APPLY ((4096 + 64 + 256 * 65) * 4)   // 83200 bytes

__global__ __launch_bounds__(256)
void apply_kernel2()
{
    extern __shared__ float sm[];
    float* kv_s = sm;
    float* ks_s = sm + 4096;
    float* q_s  = sm + 4096 + 64;   // [256][65]

    const int lt = blockIdx.x, bh = blockIdx.y;
    const int b = bh >> 4, head = bh & 15;
    const int tid = threadIdx.x;

    const float* kvsrc = g_kv + (size_t)bh * DH * DH;
    for (int i = tid; i < DH * DH / 4; i += 256)
        ((float4*)kv_s)[i] = ((const float4*)kvsrc)[i];
    if (tid < DH) ks_s[tid] = g_ksum[(size_t)bh * DH + tid];

    const size_t rowbase = (size_t)b * LL + (size_t)lt * 256;
    const float* qsrc = g_qkv + rowbase * N3D + head * DH;
    for (int i = tid; i < 256 * 16; i += 256) {
        int r = i >> 4, c = (i & 15) * 4;
        float4 v = *(const float4*)(qsrc + (size_t)r * N3D + c);
        float* qd = q_s + r * 65 + c;
        qd[0] = v.x; qd[1] = v.y; qd[2] = v.z; qd[3] = v.w;
    }
    __syncthreads();

    const int rt = tid >> 2, ct = tid & 3;
    const int r0 = rt * 4, c0 = ct * 16;

    float acc[4][16];
    #pragma unroll
    for (int i = 0; i < 4; i++)
        #pragma unroll
        for (int j = 0; j < 16; j++) acc[i][j] = 0.0f;
    float dot[4] = {0.f, 0.f, 0.f, 0.f};

    for (int d = 0; d < DH; d++) {
        float kvv[16];
        #pragma unroll
        for (int j = 0; j < 16; j += 4)
            *(float4*)&kvv[j] = *(const float4*)&kv_s[d * 64 + c0 + j];
        const float kss = ks_s[d];
        #pragma unroll
        for (int i = 0; i < 4; i++) {
            float qv = q_s[(r0 + i) * 65 + d];
            dot[i] += qv * kss;
            #pragma unroll
            for (int j = 0; j < 16; j++) acc[i][j] += qv * kvv[j];
        }
    }

    #pragma unroll
    for (int i = 0; i < 4; i++) {
        const float z = 1.0f / (dot[i] + 1e-6f);
        const size_t row = rowbase + r0 + i;
        union { __nv_bfloat16 b[8]; uint4 u; } H0, H1, L0, L1;
        #pragma unroll
        for (int j = 0; j < 16; j++) {
            float v = acc[i][j] * z;
            __nv_bfloat16 h = __float2bfloat16(v);
            __nv_bfloat16 l = __float2bfloat16(v - __bfloat162float(h));
            if (j < 8) { H0.b[j] = h; L0.b[j] = l; }
            else       { H1.b[j - 8] = h; L1.b[j - 8] = l; }
        }
        const size_t o = row * DD + head * DH + c0;
        *(uint4*)(g_yhi + o)     = H0.u;
        *(uint4*)(g_yhi + o + 8) = H1.u;
        *(uint4*)(g_ylo + o)     = L0.u;
        *(uint4*)(g_ylo + o + 8) = L1.u;
    }
}

// ---------------- launch ----------------
extern "C" void kernel_launch(void* const* d_in, const int* in_sizes, int n_in,
                              void* d_out, int out_size)
{
    (void)in_sizes; (void)n_in; (void)out_size;
    const float* x    = (const float*)d_in[0];
    const int*   mask = (const int*)  d_in[1];
    const float* Wqkv = (const float*)d_in[2];
    const float* Wout = (const float*)d_in[3];
    float* out = (float*)d_out;

    __nv_bfloat16 *xhi, *xlo, *whi, *wlo, *yhi, *ylo, *wohi, *wolo;
    float *qkv_p;
    cudaGetSymbolAddress((void**)&xhi,  g_xhi);
    cudaGetSymbolAddress((void**)&xlo,  g_xlo);
    cudaGetSymbolAddress((void**)&whi,  g_whi);
    cudaGetSymbolAddress((void**)&wlo,  g_wlo);
    cudaGetSymbolAddress((void**)&yhi,  g_yhi);
    cudaGetSymbolAddress((void**)&ylo,  g_ylo);
    cudaGetSymbolAddress((void**)&wohi, g_wohi);
    cudaGetSymbolAddress((void**)&wolo, g_wolo);
    cudaGetSymbolAddress((void**)&qkv_p, g_qkv);

    cudaFuncSetAttribute(gemm_bf16_split<1>, cudaFuncAttributeMaxDynamicSharedMemorySize, SMEM_GEMM);
    cudaFuncSetAttribute(gemm_bf16_split<2>, cudaFuncAttributeMaxDynamicSharedMemorySize, SMEM_GEMM);
    cudaFuncSetAttribute(apply_kernel2,      cudaFuncAttributeMaxDynamicSharedMemorySize, SMEM_APPLY);

    // split inputs
    conv_split<<<(MM * DD / 4 + 255) / 256, 256>>>(x, xhi, xlo, MM * DD / 4);
    conv_wT<<<dim3(N3D / 32, DD / 32), dim3(32, 8)>>>(Wqkv, whi, wlo, DD, N3D);
    conv_wT<<<dim3(DD / 32, DD / 32), dim3(32, 8)>>>(Wout, wohi, wolo, DD, DD);

    // G1: qkv = x @ Wqkv (split-bf16 mma.sync) with phi/mask epilogue
    gemm_bf16_split<1><<<dim3(N3D / 128, MM / 128), 256, SMEM_GEMM>>>(
        xhi, xlo, whi, wlo, qkv_p, N3D, DD, mask);

    // S2: kv/ksum
    kv_partial_kernel<<<dim3(NBH, NCHUNK), 256>>>();
    kv_final_kernel<<<NBH, 256>>>();

    // S3: y = (q @ kv) * z  -> bf16 hi/lo
    apply_kernel2<<<dim3(LL / 256, NBH), 256, SMEM_APPLY>>>();

    // G2: out = (y @ Wout) * mask
    gemm_bf16_split<2><<<dim3(DD / 128, MM / 128), 256, SMEM_GEMM>>>(
        yhi, ylo, wohi, wolo, out, DD, DD, mask);
}

// round 7
// speedup vs baseline: 2.7647x; 1.0610x over previous
#include <cuda_runtime.h>
#include <cuda_bf16.h>
#include <cstdint>
#include <math.h>

// ---------------- problem constants ----------------
#define BB   4
#define LL   8192
#define DD   1024
#define HH   16
#define DH   64
#define MM   (BB*LL)       // 32768
#define N3D  (3*DD)        // 3072
#define NCHUNK 8
#define CHUNK (LL/NCHUNK)  // 1024
#define NBH  (BB*HH)       // 64

// ---------------- scratch ----------------
__device__ float g_qkv[(size_t)MM * N3D];                                    // phi(q) | phi(k)*m | v*m
__device__ __nv_bfloat16 g_xhi[(size_t)MM * DD], g_xlo[(size_t)MM * DD];
__device__ __nv_bfloat16 g_whi[(size_t)N3D * DD], g_wlo[(size_t)N3D * DD];   // Wqkv^T [N,K]
__device__ __nv_bfloat16 g_qphi[(size_t)MM * DD], g_qplo[(size_t)MM * DD];   // q' = z*q, hi/lo
__device__ __nv_bfloat16 g_mhi[(size_t)BB * DD * DD], g_mlo[(size_t)BB * DD * DD]; // M_b^T [b][n][hd]
__device__ float g_kv_part[(size_t)NCHUNK * NBH * DH * DH];
__device__ float g_ksum_part[(size_t)NCHUNK * NBH * DH];
__device__ float g_kv[(size_t)NBH * DH * DH];
__device__ float g_ksum[(size_t)NBH * DH];

// ---------------- helpers ----------------
__device__ __forceinline__ uint32_t smem_u32(const void* p) {
    uint32_t a;
    asm("{ .reg .u64 t; cvta.to.shared.u64 t, %1; cvt.u32.u64 %0, t; }" : "=r"(a) : "l"(p));
    return a;
}
#define CP_ASYNC16(sa, ga) asm volatile("cp.async.cg.shared.global [%0], [%1], 16;" :: "r"(sa), "l"(ga))
#define CP_COMMIT()        asm volatile("cp.async.commit_group;" ::: "memory")
#define CP_WAIT(n)         asm volatile("cp.async.wait_group %0;" :: "n"(n) : "memory")

#define LDMX4(r0, r1, r2, r3, a) \
    asm volatile("ldmatrix.sync.aligned.m8n8.x4.shared.b16 {%0,%1,%2,%3}, [%4];" \
        : "=r"(r0), "=r"(r1), "=r"(r2), "=r"(r3) : "r"(a))

#define MMA16816(c, a, b0, b1) \
    asm volatile("mma.sync.aligned.m16n8k16.row.col.f32.bf16.bf16.f32 " \
        "{%0,%1,%2,%3}, {%4,%5,%6,%7}, {%8,%9}, {%0,%1,%2,%3};" \
        : "+f"((c)[0]), "+f"((c)[1]), "+f"((c)[2]), "+f"((c)[3]) \
        : "r"((a)[0]), "r"((a)[1]), "r"((a)[2]), "r"((a)[3]), "r"(b0), "r"(b1))

__device__ __forceinline__ float phi_f(float z) { return z > 0.0f ? z + 1.0f : expf(z); }

// ---------------- split conversion kernels ----------------
__global__ void conv_split(const float* __restrict__ in, __nv_bfloat16* __restrict__ hi,
                           __nv_bfloat16* __restrict__ lo, int n4)
{
    int i = blockIdx.x * 256 + threadIdx.x;
    if (i >= n4) return;
    float4 v = ((const float4*)in)[i];
    float f[4] = {v.x, v.y, v.z, v.w};
    union { __nv_bfloat16 b[4]; uint2 u; } H, L;
    #pragma unroll
    for (int j = 0; j < 4; j++) {
        __nv_bfloat16 h = __float2bfloat16(f[j]);
        H.b[j] = h;
        L.b[j] = __float2bfloat16(f[j] - __bfloat162float(h));
    }
    ((uint2*)hi)[i] = H.u;
    ((uint2*)lo)[i] = L.u;
}

// W [R,C] row-major -> out [C,R] bf16 hi/lo
__global__ void conv_wT(const float* __restrict__ W, __nv_bfloat16* __restrict__ hi,
                        __nv_bfloat16* __restrict__ lo, int R, int Ccols)
{
    __shared__ float t[32][33];
    int cx = blockIdx.x * 32, rx = blockIdx.y * 32;
    for (int i = threadIdx.y; i < 32; i += 8)
        t[i][threadIdx.x] = W[(size_t)(rx + i) * Ccols + cx + threadIdx.x];
    __syncthreads();
    for (int i = threadIdx.y; i < 32; i += 8) {
        float v = t[threadIdx.x][i];
        __nv_bfloat16 h = __float2bfloat16(v);
        size_t o = (size_t)(cx + i) * R + rx + threadIdx.x;
        hi[o] = h;
        lo[o] = __float2bfloat16(v - __bfloat162float(h));
    }
}

// ---------------- mma.sync split-bf16 GEMM (fused 3-product steps) ----------------
// C[M,N] = Ahi*Bhi + Ahi*Blo + Alo*Bhi ; A [M,K] K-major, B [N,K] K-major, K=1024.
// Tile 128x128, BK=32, 8 warps (4m x 2n), warp tile 32x64.
// EPI==1: qkv epilogue. EPI==2: *mask epilogue with per-batch B (b = m0>>13).
#define ROWB 80
#define TILE_B (128 * ROWB)            // 10240 per sub-tile
#define STAGE_B (4 * TILE_B)           // 40960 (AH|AL|BH|BL)
#define SMEM_GEMM (2 * STAGE_B)        // 81920
#define KSTEPS 32                      // K=1024, BK=32

__device__ __forceinline__ void g_load4(uint32_t sbuf,
    const __nv_bfloat16* __restrict__ Ahi, const __nv_bfloat16* __restrict__ Alo,
    const __nv_bfloat16* __restrict__ Bhi, const __nv_bfloat16* __restrict__ Blo,
    int m0, int n0, int K, int kk, int tid)
{
    #pragma unroll
    for (int i = 0; i < 2; i++) {
        int id = tid + i * 256;              // 0..511
        int row = id >> 2, ch = id & 3;      // 128 rows x 4 16B-chunks
        uint32_t so = (uint32_t)(row * ROWB + ch * 16);
        size_t ga = (size_t)(m0 + row) * K + kk + ch * 8;
        size_t gb = (size_t)(n0 + row) * K + kk + ch * 8;
        CP_ASYNC16(sbuf + so,              (const char*)(Ahi + ga));
        CP_ASYNC16(sbuf + TILE_B + so,     (const char*)(Alo + ga));
        CP_ASYNC16(sbuf + 2 * TILE_B + so, (const char*)(Bhi + gb));
        CP_ASYNC16(sbuf + 3 * TILE_B + so, (const char*)(Blo + gb));
    }
}

template<int EPI>
__global__ __launch_bounds__(256, 2)
void gemm_bf16_split(const __nv_bfloat16* __restrict__ Ahi, const __nv_bfloat16* __restrict__ Alo,
                     const __nv_bfloat16* __restrict__ Bhi_in, const __nv_bfloat16* __restrict__ Blo_in,
                     float* __restrict__ C, int N, int K, const int* __restrict__ mask)
{
    extern __shared__ char smem[];
    const uint32_t sb = smem_u32(smem);
    const int tid = threadIdx.x;
    const int wid = tid >> 5, lane = tid & 31;
    const int wm = wid & 3, wn = wid >> 2;
    const int m0 = blockIdx.y * 128, n0 = blockIdx.x * 128;

    const __nv_bfloat16* Bhi = Bhi_in;
    const __nv_bfloat16* Blo = Blo_in;
    if (EPI == 2) {   // per-batch B: M_b stacked [BB][N][K]
        size_t boff = (size_t)(m0 >> 13) * N * K;
        Bhi += boff;  Blo += boff;
    }

    float acc[2][8][4];
    #pragma unroll
    for (int mi = 0; mi < 2; mi++)
        #pragma unroll
        for (int j = 0; j < 8; j++)
            #pragma unroll
            for (int e = 0; e < 4; e++) acc[mi][j][e] = 0.0f;

    const uint32_t a_off = (uint32_t)((wm * 32 + (lane & 15)) * ROWB + (lane >> 4) * 16);
    const uint32_t b_off = (uint32_t)((wn * 64 + ((lane >> 4) & 1) * 8 + (lane & 7)) * ROWB
                                      + ((lane >> 3) & 1) * 16);

    g_load4(sb, Ahi, Alo, Bhi, Blo, m0, n0, K, 0, tid);
    CP_COMMIT();

    for (int s = 0; s < KSTEPS; s++) {
        CP_WAIT(0);
        __syncthreads();
        if (s + 1 < KSTEPS) {
            g_load4(sb + ((s + 1) & 1) * STAGE_B, Ahi, Alo, Bhi, Blo, m0, n0, K, (s + 1) * 32, tid);
            CP_COMMIT();
        }
        const uint32_t st = sb + (s & 1) * STAGE_B;
        #pragma unroll
        for (int c = 0; c < 2; c++) {
            const uint32_t sAH = st + a_off + c * 32;
            const uint32_t sAL = st + TILE_B + a_off + c * 32;
            const uint32_t sBH = st + 2 * TILE_B + b_off + c * 32;
            const uint32_t sBL = st + 3 * TILE_B + b_off + c * 32;

            uint32_t aH[2][4], bH[4][4];
            LDMX4(aH[0][0], aH[0][1], aH[0][2], aH[0][3], sAH);
            LDMX4(aH[1][0], aH[1][1], aH[1][2], aH[1][3], sAH + 16 * ROWB);
            #pragma unroll
            for (int jp = 0; jp < 4; jp++)
                LDMX4(bH[jp][0], bH[jp][1], bH[jp][2], bH[jp][3], sBH + jp * (16 * ROWB));

            // aH * bH
            #pragma unroll
            for (int mi = 0; mi < 2; mi++)
                #pragma unroll
                for (int j = 0; j < 8; j++) {
                    const uint32_t* bp = bH[j >> 1];
                    if (j & 1) MMA16816(acc[mi][j], aH[mi], bp[2], bp[3]);
                    else       MMA16816(acc[mi][j], aH[mi], bp[0], bp[1]);
                }

            // aH * bL
            {
                uint32_t bL[4][4];
                #pragma unroll
                for (int jp = 0; jp < 4; jp++)
                    LDMX4(bL[jp][0], bL[jp][1], bL[jp][2], bL[jp][3], sBL + jp * (16 * ROWB));
                #pragma unroll
                for (int mi = 0; mi < 2; mi++)
                    #pragma unroll
                    for (int j = 0; j < 8; j++) {
                        const uint32_t* bp = bL[j >> 1];
                        if (j & 1) MMA16816(acc[mi][j], aH[mi], bp[2], bp[3]);
                        else       MMA16816(acc[mi][j], aH[mi], bp[0], bp[1]);
                    }
            }

            // aL * bH
            {
                uint32_t aL[2][4];
                LDMX4(aL[0][0], aL[0][1], aL[0][2], aL[0][3], sAL);
                LDMX4(aL[1][0], aL[1][1], aL[1][2], aL[1][3], sAL + 16 * ROWB);
                #pragma unroll
                for (int mi = 0; mi < 2; mi++)
                    #pragma unroll
                    for (int j = 0; j < 8; j++) {
                        const uint32_t* bp = bH[j >> 1];
                        if (j & 1) MMA16816(acc[mi][j], aL[mi], bp[2], bp[3]);
                        else       MMA16816(acc[mi][j], aL[mi], bp[0], bp[1]);
                    }
            }
        }
    }

    // epilogue
    const int gr = lane >> 2, tc = lane & 3;
    const int region = n0 >> 10;   // 0=q, 1=k, 2=v (EPI==1)
    #pragma unroll
    for (int mi = 0; mi < 2; mi++) {
        const int rbase = m0 + wm * 32 + mi * 16 + gr;
        float mv0 = 1.0f, mv1 = 1.0f;
        if (EPI > 0) { mv0 = (float)mask[rbase]; mv1 = (float)mask[rbase + 8]; }
        #pragma unroll
        for (int j = 0; j < 8; j++) {
            const int col = n0 + wn * 64 + j * 8 + tc * 2;
            float v0 = acc[mi][j][0], v1 = acc[mi][j][1];
            float v2 = acc[mi][j][2], v3 = acc[mi][j][3];
            if (EPI == 1) {
                if (region == 0)      { v0 = phi_f(v0); v1 = phi_f(v1); v2 = phi_f(v2); v3 = phi_f(v3); }
                else if (region == 1) { v0 = phi_f(v0) * mv0; v1 = phi_f(v1) * mv0;
                                        v2 = phi_f(v2) * mv1; v3 = phi_f(v3) * mv1; }
                else                  { v0 *= mv0; v1 *= mv0; v2 *= mv1; v3 *= mv1; }
            } else if (EPI == 2) { v0 *= mv0; v1 *= mv0; v2 *= mv1; v3 *= mv1; }
            float2 p0 = make_float2(v0, v1), p1 = make_float2(v2, v3);
            *(float2*)(C + (size_t)rbase * N + col)       = p0;
            *(float2*)(C + (size_t)(rbase + 8) * N + col) = p1;
        }
    }
}

// ---------------- Stage 2: kv / ksum partials (cp.async double buffered) ----------------
#define KVROWS 32
__global__ __launch_bounds__(256)
void kv_partial_kernel()
{
    const int bh = blockIdx.x, chunk = blockIdx.y;
    const int b = bh / HH, h = bh % HH;
    const int tid = threadIdx.x;
    const int ty = tid >> 4, tx = tid & 15;

    __shared__ float ks[2][KVROWS][DH];
    __shared__ float vs[2][KVROWS][DH];

    const size_t rowbase = (size_t)b * LL + (size_t)chunk * CHUNK;
    const float* kptr = g_qkv + rowbase * N3D + DD     + h * DH;
    const float* vptr = g_qkv + rowbase * N3D + 2 * DD + h * DH;

    const uint32_t ksb = smem_u32(&ks[0][0][0]);
    const uint32_t vsb = smem_u32(&vs[0][0][0]);

    auto issue = [&](int buf, int l0) {
        #pragma unroll
        for (int i = 0; i < 2; i++) {
            int id  = tid + i * 256;
            int row = id >> 4, ch = id & 15;
            uint32_t so = (uint32_t)(buf * KVROWS * DH * 4 + row * DH * 4 + ch * 16);
            CP_ASYNC16(ksb + so, (const char*)(kptr + (size_t)(l0 + row) * N3D + ch * 4));
            CP_ASYNC16(vsb + so, (const char*)(vptr + (size_t)(l0 + row) * N3D + ch * 4));
        }
        CP_COMMIT();
    };

    float acc[4][4];
    #pragma unroll
    for (int i = 0; i < 4; i++)
        #pragma unroll
        for (int j = 0; j < 4; j++) acc[i][j] = 0.0f;
    float ksacc[4] = {0.f, 0.f, 0.f, 0.f};

    issue(0, 0);
    const int NIT = CHUNK / KVROWS;
    for (int it = 0; it < NIT; it++) {
        CP_WAIT(0);
        __syncthreads();
        if (it + 1 < NIT) issue((it + 1) & 1, (it + 1) * KVROWS);
        const int buf = it & 1;
        #pragma unroll 8
        for (int r = 0; r < KVROWS; r++) {
            float kr[4], vr[4];
            *(float4*)kr = *(const float4*)&ks[buf][r][ty * 4];
            *(float4*)vr = *(const float4*)&vs[buf][r][tx * 4];
            #pragma unroll
            for (int i = 0; i < 4; i++)
                #pragma unroll
                for (int j = 0; j < 4; j++)
                    acc[i][j] += kr[i] * vr[j];
            if (tx == 0) {
                #pragma unroll
                for (int i = 0; i < 4; i++) ksacc[i] += kr[i];
            }
        }
        __syncthreads();
    }

    float* out = g_kv_part + ((size_t)chunk * NBH + bh) * DH * DH;
    #pragma unroll
    for (int i = 0; i < 4; i++)
        #pragma unroll
        for (int j = 0; j < 4; j++)
            out[(ty * 4 + i) * DH + tx * 4 + j] = acc[i][j];
    if (tx == 0) {
        float* ko = g_ksum_part + ((size_t)chunk * NBH + bh) * DH;
        #pragma unroll
        for (int i = 0; i < 4; i++) ko[ty * 4 + i] = ksacc[i];
    }
}

__global__ void kv_final_kernel()
{
    const int bh = blockIdx.x;
    for (int idx = threadIdx.x; idx < DH * DH; idx += blockDim.x) {
        float s = 0.0f;
        #pragma unroll
        for (int c = 0; c < NCHUNK; c++)
            s += g_kv_part[((size_t)c * NBH + bh) * DH * DH + idx];
        g_kv[(size_t)bh * DH * DH + idx] = s;
    }
    for (int idx = threadIdx.x; idx < DH; idx += blockDim.x) {
        float s = 0.0f;
        #pragma unroll
        for (int c = 0; c < NCHUNK; c++)
            s += g_ksum_part[((size_t)c * NBH + bh) * DH + idx];
        g_ksum[(size_t)bh * DH + idx] = s;
    }
}

// ---------------- zq: z = 1/(q.ksum + eps) per (l,h); q' = z*q -> bf16 hi/lo ----------------
__global__ __launch_bounds__(256)
void zq_kernel()
{
    __shared__ float qrow[DD];
    __shared__ float zs[HH];

    const int r = blockIdx.x;          // global row 0..32767
    const int b = r >> 13;
    const int tid = threadIdx.x;
    const int wid = tid >> 5, lane = tid & 31;

    // load q row (region 0 of g_qkv)
    const float* qsrc = g_qkv + (size_t)r * N3D;
    ((float4*)qrow)[tid] = ((const float4*)qsrc)[tid];
    __syncthreads();

    // warp w computes heads 2w and 2w+1
    #pragma unroll
    for (int hh = 2 * wid; hh < 2 * wid + 2; hh++) {
        const float* ks = g_ksum + ((size_t)b * HH + hh) * DH;
        float v = qrow[hh * DH + lane] * ks[lane]
                + qrow[hh * DH + 32 + lane] * ks[32 + lane];
        #pragma unroll
        for (int o = 16; o > 0; o >>= 1)
            v += __shfl_xor_sync(0xFFFFFFFF, v, o);
        if (lane == 0) zs[hh] = 1.0f / (v + 1e-6f);
    }
    __syncthreads();

    // write q' = z*q as bf16 hi/lo (4 elems per thread, all within one head)
    const int c = tid * 4;
    const float z = zs[c >> 6];
    union { __nv_bfloat16 b[4]; uint2 u; } H, L;
    #pragma unroll
    for (int j = 0; j < 4; j++) {
        float v = qrow[c + j] * z;
        __nv_bfloat16 h = __float2bfloat16(v);
        H.b[j] = h;
        L.b[j] = __float2bfloat16(v - __bfloat162float(h));
    }
    ((uint2*)(g_qphi + (size_t)r * DD))[tid] = H.u;
    ((uint2*)(g_qplo + (size_t)r * DD))[tid] = L.u;
}

// ---------------- M: M_T[b][n][h*64+d] = sum_m kv[b,h,d,m] * Wout[h*64+m, n] ----------------
// grid (NBH, DD/64), 256 threads. thread: d = tid&63, ng = tid>>6 (16 n's each).
// smem: kv 16.6KB + w 16KB = 32.6KB (under 48KB static limit).
__global__ __launch_bounds__(256)
void m_kernel(const float* __restrict__ Wout)
{
    __shared__ float kv_s[DH * 65];      // padded rows
    __shared__ float w_s[DH * 64];

    const int bh = blockIdx.x;
    const int b = bh >> 4, h = bh & 15;
    const int n0 = blockIdx.y * 64;
    const int tid = threadIdx.x;

    for (int i = tid; i < DH * DH; i += 256)
        kv_s[(i >> 6) * 65 + (i & 63)] = g_kv[(size_t)bh * DH * DH + i];
    for (int i = tid; i < DH * 64; i += 256) {
        int m = i >> 6, n = i & 63;
        w_s[m * 64 + n] = Wout[(size_t)(h * DH + m) * DD + n0 + n];
    }
    __syncthreads();

    const int d = tid & 63, ng = tid >> 6;   // ng 0..3, n's = ng*16 .. ng*16+15
    float acc[16];
    #pragma unroll
    for (int j = 0; j < 16; j++) acc[j] = 0.0f;

    for (int m = 0; m < DH; m++) {
        const float kvd = kv_s[d * 65 + m];
        const float* wr = w_s + m * 64 + ng * 16;
        #pragma unroll
        for (int j = 0; j < 16; j += 4) {
            float4 w4 = *(const float4*)(wr + j);
            acc[j + 0] += kvd * w4.x;
            acc[j + 1] += kvd * w4.y;
            acc[j + 2] += kvd * w4.z;
            acc[j + 3] += kvd * w4.w;
        }
    }

    #pragma unroll
    for (int j = 0; j < 16; j++) {
        const int n = n0 + ng * 16 + j;
        const size_t o = ((size_t)b * DD + n) * DD + h * DH + d;
        float v = acc[j];
        __nv_bfloat16 hh = __float2bfloat16(v);
        g_mhi[o] = hh;
        g_mlo[o] = __float2bfloat16(v - __bfloat162float(hh));
    }
}

// ---------------- launch ----------------
extern "C" void kernel_launch(void* const* d_in, const int* in_sizes, int n_in,
                              void* d_out, int out_size)
{
    (void)in_sizes; (void)n_in; (void)out_size;
    const float* x    = (const float*)d_in[0];
    const int*   mask = (const int*)  d_in[1];
    const float* Wqkv = (const float*)d_in[2];
    const float* Wout = (const float*)d_in[3];
    float* out = (float*)d_out;

    __nv_bfloat16 *xhi, *xlo, *whi, *wlo, *qphi, *qplo, *mhi, *mlo;
    float *qkv_p;
    cudaGetSymbolAddress((void**)&xhi,  g_xhi);
    cudaGetSymbolAddress((void**)&xlo,  g_xlo);
    cudaGetSymbolAddress((void**)&whi,  g_whi);
    cudaGetSymbolAddress((void**)&wlo,  g_wlo);
    cudaGetSymbolAddress((void**)&qphi, g_qphi);
    cudaGetSymbolAddress((void**)&qplo, g_qplo);
    cudaGetSymbolAddress((void**)&mhi,  g_mhi);
    cudaGetSymbolAddress((void**)&mlo,  g_mlo);
    cudaGetSymbolAddress((void**)&qkv_p, g_qkv);

    cudaFuncSetAttribute(gemm_bf16_split<1>, cudaFuncAttributeMaxDynamicSharedMemorySize, SMEM_GEMM);
    cudaFuncSetAttribute(gemm_bf16_split<2>, cudaFuncAttributeMaxDynamicSharedMemorySize, SMEM_GEMM);

    // split inputs
    conv_split<<<(MM * DD / 4 + 255) / 256, 256>>>(x, xhi, xlo, MM * DD / 4);
    conv_wT<<<dim3(N3D / 32, DD / 32), dim3(32, 8)>>>(Wqkv, whi, wlo, DD, N3D);

    // G1: qkv = x @ Wqkv (split-bf16 mma.sync) with phi/mask epilogue
    gemm_bf16_split<1><<<dim3(N3D / 128, MM / 128), 256, SMEM_GEMM>>>(
        xhi, xlo, whi, wlo, qkv_p, N3D, DD, mask);

    // S2: kv/ksum
    kv_partial_kernel<<<dim3(NBH, NCHUNK), 256>>>();
    kv_final_kernel<<<NBH, 256>>>();

    // z + q' = z*q -> bf16 hi/lo
    zq_kernel<<<MM, 256>>>();

    // M_b^T = (kv_b @ Wout-blocks)^T -> bf16 hi/lo
    m_kernel<<<dim3(NBH, DD / 64), 256>>>(Wout);

    // G2: out = (q' @ M_b) * mask
    gemm_bf16_split<2><<<dim3(DD / 128, MM / 128), 256, SMEM_GEMM>>>(
        qphi, qplo, mhi, mlo, out, DD, DD, mask);
}

// round 8
// speedup vs baseline: 4.7729x; 1.7264x over previous
#include <cuda_runtime.h>
#include <cuda_bf16.h>
#include <cstdint>
#include <math.h>

// ---------------- problem constants ----------------
#define BB   4
#define LL   8192
#define DD   1024
#define HH   16
#define DH   64
#define MM   (BB*LL)       // 32768
#define N3D  (3*DD)        // 3072
#define NCHUNK 8
#define CHUNK (LL/NCHUNK)  // 1024
#define NBH  (BB*HH)       // 64

// ---------------- scratch ----------------
__device__ float g_qkv[(size_t)MM * N3D];                                    // compacted: phi(q) | phi(k)*m | v*m
__device__ __nv_bfloat16 g_xhi[(size_t)MM * DD], g_xlo[(size_t)MM * DD];     // compacted x
__device__ __nv_bfloat16 g_whi[(size_t)N3D * DD], g_wlo[(size_t)N3D * DD];   // Wqkv^T [N,K]
__device__ __nv_bfloat16 g_qphi[(size_t)MM * DD], g_qplo[(size_t)MM * DD];   // q' = z*q (compacted)
__device__ __nv_bfloat16 g_mhi[(size_t)BB * DD * DD], g_mlo[(size_t)BB * DD * DD]; // M_b^T
__device__ float g_kv_part[(size_t)NCHUNK * NBH * DH * DH];
__device__ float g_ksum_part[(size_t)NCHUNK * NBH * DH];
__device__ float g_kv[(size_t)NBH * DH * DH];
__device__ float g_ksum[(size_t)NBH * DH];
// compaction state
__device__ int g_idx[MM];     // compacted j -> original global row
__device__ int g_cmask[MM];   // 1 = real row, 0 = padding
__device__ int g_npad[BB];    // active rows per batch, padded to 128

// ---------------- helpers ----------------
__device__ __forceinline__ uint32_t smem_u32(const void* p) {
    uint32_t a;
    asm("{ .reg .u64 t; cvta.to.shared.u64 t, %1; cvt.u32.u64 %0, t; }" : "=r"(a) : "l"(p));
    return a;
}
#define CP_ASYNC16(sa, ga) asm volatile("cp.async.cg.shared.global [%0], [%1], 16;" :: "r"(sa), "l"(ga))
#define CP_COMMIT()        asm volatile("cp.async.commit_group;" ::: "memory")
#define CP_WAIT(n)         asm volatile("cp.async.wait_group %0;" :: "n"(n) : "memory")

#define LDMX4(r0, r1, r2, r3, a) \
    asm volatile("ldmatrix.sync.aligned.m8n8.x4.shared.b16 {%0,%1,%2,%3}, [%4];" \
        : "=r"(r0), "=r"(r1), "=r"(r2), "=r"(r3) : "r"(a))

#define MMA16816(c, a, b0, b1) \
    asm volatile("mma.sync.aligned.m16n8k16.row.col.f32.bf16.bf16.f32 " \
        "{%0,%1,%2,%3}, {%4,%5,%6,%7}, {%8,%9}, {%0,%1,%2,%3};" \
        : "+f"((c)[0]), "+f"((c)[1]), "+f"((c)[2]), "+f"((c)[3]) \
        : "r"((a)[0]), "r"((a)[1]), "r"((a)[2]), "r"((a)[3]), "r"(b0), "r"(b1))

__device__ __forceinline__ float phi_f(float z) { return z > 0.0f ? z + 1.0f : expf(z); }

// ---------------- compaction scan (deterministic) ----------------
// grid BB, block 1024; thread t owns local rows t*8..t*8+7.
__global__ __launch_bounds__(1024)
void scan_kernel(const int* __restrict__ mask)
{
    __shared__ int warp_sums[32];
    const int b = blockIdx.x, tid = threadIdx.x;
    const int base = b * LL;
    const int lane = tid & 31, wid = tid >> 5;

    int vals[8], s = 0;
    #pragma unroll
    for (int j = 0; j < 8; j++) { vals[j] = mask[base + tid * 8 + j]; s += vals[j]; }

    int ssum = s;
    #pragma unroll
    for (int o = 1; o < 32; o <<= 1) {
        int v = __shfl_up_sync(0xFFFFFFFF, ssum, o);
        if (lane >= o) ssum += v;
    }
    if (lane == 31) warp_sums[wid] = ssum;
    __syncthreads();
    if (wid == 0) {
        int w = warp_sums[lane];
        #pragma unroll
        for (int o = 1; o < 32; o <<= 1) {
            int v = __shfl_up_sync(0xFFFFFFFF, w, o);
            if (lane >= o) w += v;
        }
        warp_sums[lane] = w;
    }
    __syncthreads();

    int pos = (ssum - s) + (wid > 0 ? warp_sums[wid - 1] : 0);
    #pragma unroll
    for (int j = 0; j < 8; j++) {
        if (vals[j]) {
            g_idx[base + pos] = base + tid * 8 + j;
            g_cmask[base + pos] = 1;
            pos++;
        }
    }
    __syncthreads();
    const int total = warp_sums[31];
    const int npad = (total + 127) & ~127;
    if (tid == 0) g_npad[b] = npad;
    for (int p = total + tid; p < npad; p += 1024) {
        g_idx[base + p] = base;     // valid address; never stored (cmask=0)
        g_cmask[base + p] = 0;
    }
}

// ---------------- zero d_out ----------------
__global__ void zero_out(float* __restrict__ out)
{
    size_t i = (size_t)blockIdx.x * 256 + threadIdx.x;
    ((float4*)out)[i] = make_float4(0.f, 0.f, 0.f, 0.f);
}

// ---------------- gather + split x (compacted) ----------------
// grid MM (compacted rows), block 256; 4 elems/thread.
__global__ __launch_bounds__(256)
void conv_gather_x(const float* __restrict__ x)
{
    const int j = blockIdx.x;
    const int b = j >> 13;
    if ((j & (LL - 1)) >= g_npad[b]) return;
    const int tid = threadIdx.x;

    union { __nv_bfloat16 b[4]; uint2 u; } H, L;
    if (g_cmask[j]) {
        const float* src = x + (size_t)g_idx[j] * DD + tid * 4;
        float4 v = *(const float4*)src;
        float f[4] = {v.x, v.y, v.z, v.w};
        #pragma unroll
        for (int e = 0; e < 4; e++) {
            __nv_bfloat16 h = __float2bfloat16(f[e]);
            H.b[e] = h;
            L.b[e] = __float2bfloat16(f[e] - __bfloat162float(h));
        }
    } else {
        H.u = make_uint2(0, 0);
        L.u = make_uint2(0, 0);
    }
    ((uint2*)(g_xhi + (size_t)j * DD))[tid] = H.u;
    ((uint2*)(g_xlo + (size_t)j * DD))[tid] = L.u;
}

// W [R,C] row-major -> out [C,R] bf16 hi/lo
__global__ void conv_wT(const float* __restrict__ W, __nv_bfloat16* __restrict__ hi,
                        __nv_bfloat16* __restrict__ lo, int R, int Ccols)
{
    __shared__ float t[32][33];
    int cx = blockIdx.x * 32, rx = blockIdx.y * 32;
    for (int i = threadIdx.y; i < 32; i += 8)
        t[i][threadIdx.x] = W[(size_t)(rx + i) * Ccols + cx + threadIdx.x];
    __syncthreads();
    for (int i = threadIdx.y; i < 32; i += 8) {
        float v = t[threadIdx.x][i];
        __nv_bfloat16 h = __float2bfloat16(v);
        size_t o = (size_t)(cx + i) * R + rx + threadIdx.x;
        hi[o] = h;
        lo[o] = __float2bfloat16(v - __bfloat162float(h));
    }
}

// ---------------- mma.sync split-bf16 GEMM (fused 3-product steps, compacted rows) ----------------
// EPI==1: qkv epilogue (phi / phi*cmask / *cmask). EPI==2: scatter to out[g_idx[j]] if cmask.
#define ROWB 80
#define TILE_B (128 * ROWB)
#define STAGE_B (4 * TILE_B)
#define SMEM_GEMM (2 * STAGE_B)        // 81920
#define KSTEPS 32

__device__ __forceinline__ void g_load4(uint32_t sbuf,
    const __nv_bfloat16* __restrict__ Ahi, const __nv_bfloat16* __restrict__ Alo,
    const __nv_bfloat16* __restrict__ Bhi, const __nv_bfloat16* __restrict__ Blo,
    int m0, int n0, int K, int kk, int tid)
{
    #pragma unroll
    for (int i = 0; i < 2; i++) {
        int id = tid + i * 256;
        int row = id >> 2, ch = id & 3;
        uint32_t so = (uint32_t)(row * ROWB + ch * 16);
        size_t ga = (size_t)(m0 + row) * K + kk + ch * 8;
        size_t gb = (size_t)(n0 + row) * K + kk + ch * 8;
        CP_ASYNC16(sbuf + so,              (const char*)(Ahi + ga));
        CP_ASYNC16(sbuf + TILE_B + so,     (const char*)(Alo + ga));
        CP_ASYNC16(sbuf + 2 * TILE_B + so, (const char*)(Bhi + gb));
        CP_ASYNC16(sbuf + 3 * TILE_B + so, (const char*)(Blo + gb));
    }
}

template<int EPI>
__global__ __launch_bounds__(256, 2)
void gemm_bf16_split(const __nv_bfloat16* __restrict__ Ahi, const __nv_bfloat16* __restrict__ Alo,
                     const __nv_bfloat16* __restrict__ Bhi_in, const __nv_bfloat16* __restrict__ Blo_in,
                     float* __restrict__ C, int N, int K)
{
    const int m0 = blockIdx.y * 128, n0 = blockIdx.x * 128;
    if ((m0 & (LL - 1)) >= g_npad[m0 >> 13]) return;   // dead row-tile

    extern __shared__ char smem[];
    const uint32_t sb = smem_u32(smem);
    const int tid = threadIdx.x;
    const int wid = tid >> 5, lane = tid & 31;
    const int wm = wid & 3, wn = wid >> 2;

    const __nv_bfloat16* Bhi = Bhi_in;
    const __nv_bfloat16* Blo = Blo_in;
    if (EPI == 2) {   // per-batch B: M_b stacked [BB][N][K]
        size_t boff = (size_t)(m0 >> 13) * N * K;
        Bhi += boff;  Blo += boff;
    }

    float acc[2][8][4];
    #pragma unroll
    for (int mi = 0; mi < 2; mi++)
        #pragma unroll
        for (int j = 0; j < 8; j++)
            #pragma unroll
            for (int e = 0; e < 4; e++) acc[mi][j][e] = 0.0f;

    const uint32_t a_off = (uint32_t)((wm * 32 + (lane & 15)) * ROWB + (lane >> 4) * 16);
    const uint32_t b_off = (uint32_t)((wn * 64 + ((lane >> 4) & 1) * 8 + (lane & 7)) * ROWB
                                      + ((lane >> 3) & 1) * 16);

    g_load4(sb, Ahi, Alo, Bhi, Blo, m0, n0, K, 0, tid);
    CP_COMMIT();

    for (int s = 0; s < KSTEPS; s++) {
        CP_WAIT(0);
        __syncthreads();
        if (s + 1 < KSTEPS) {
            g_load4(sb + ((s + 1) & 1) * STAGE_B, Ahi, Alo, Bhi, Blo, m0, n0, K, (s + 1) * 32, tid);
            CP_COMMIT();
        }
        const uint32_t st = sb + (s & 1) * STAGE_B;
        #pragma unroll
        for (int c = 0; c < 2; c++) {
            const uint32_t sAH = st + a_off + c * 32;
            const uint32_t sAL = st + TILE_B + a_off + c * 32;
            const uint32_t sBH = st + 2 * TILE_B + b_off + c * 32;
            const uint32_t sBL = st + 3 * TILE_B + b_off + c * 32;

            uint32_t aH[2][4], bH[4][4];
            LDMX4(aH[0][0], aH[0][1], aH[0][2], aH[0][3], sAH);
            LDMX4(aH[1][0], aH[1][1], aH[1][2], aH[1][3], sAH + 16 * ROWB);
            #pragma unroll
            for (int jp = 0; jp < 4; jp++)
                LDMX4(bH[jp][0], bH[jp][1], bH[jp][2], bH[jp][3], sBH + jp * (16 * ROWB));

            #pragma unroll
            for (int mi = 0; mi < 2; mi++)
                #pragma unroll
                for (int j = 0; j < 8; j++) {
                    const uint32_t* bp = bH[j >> 1];
                    if (j & 1) MMA16816(acc[mi][j], aH[mi], bp[2], bp[3]);
                    else       MMA16816(acc[mi][j], aH[mi], bp[0], bp[1]);
                }
            {
                uint32_t bL[4][4];
                #pragma unroll
                for (int jp = 0; jp < 4; jp++)
                    LDMX4(bL[jp][0], bL[jp][1], bL[jp][2], bL[jp][3], sBL + jp * (16 * ROWB));
                #pragma unroll
                for (int mi = 0; mi < 2; mi++)
                    #pragma unroll
                    for (int j = 0; j < 8; j++) {
                        const uint32_t* bp = bL[j >> 1];
                        if (j & 1) MMA16816(acc[mi][j], aH[mi], bp[2], bp[3]);
                        else       MMA16816(acc[mi][j], aH[mi], bp[0], bp[1]);
                    }
            }
            {
                uint32_t aL[2][4];
                LDMX4(aL[0][0], aL[0][1], aL[0][2], aL[0][3], sAL);
                LDMX4(aL[1][0], aL[1][1], aL[1][2], aL[1][3], sAL + 16 * ROWB);
                #pragma unroll
                for (int mi = 0; mi < 2; mi++)
                    #pragma unroll
                    for (int j = 0; j < 8; j++) {
                        const uint32_t* bp = bH[j >> 1];
                        if (j & 1) MMA16816(acc[mi][j], aL[mi], bp[2], bp[3]);
                        else       MMA16816(acc[mi][j], aL[mi], bp[0], bp[1]);
                    }
            }
        }
    }

    // epilogue
    const int gr = lane >> 2, tc = lane & 3;
    const int region = n0 >> 10;
    #pragma unroll
    for (int mi = 0; mi < 2; mi++) {
        const int rbase = m0 + wm * 32 + mi * 16 + gr;
        const int cm0 = g_cmask[rbase], cm1 = g_cmask[rbase + 8];
        const float mv0 = (float)cm0, mv1 = (float)cm1;
        #pragma unroll
        for (int j = 0; j < 8; j++) {
            const int col = n0 + wn * 64 + j * 8 + tc * 2;
            float v0 = acc[mi][j][0], v1 = acc[mi][j][1];
            float v2 = acc[mi][j][2], v3 = acc[mi][j][3];
            if (EPI == 1) {
                if (region == 0)      { v0 = phi_f(v0); v1 = phi_f(v1); v2 = phi_f(v2); v3 = phi_f(v3); }
                else if (region == 1) { v0 = phi_f(v0) * mv0; v1 = phi_f(v1) * mv0;
                                        v2 = phi_f(v2) * mv1; v3 = phi_f(v3) * mv1; }
                else                  { v0 *= mv0; v1 *= mv0; v2 *= mv1; v3 *= mv1; }
                float2 p0 = make_float2(v0, v1), p1 = make_float2(v2, v3);
                *(float2*)(C + (size_t)rbase * N + col)       = p0;
                *(float2*)(C + (size_t)(rbase + 8) * N + col) = p1;
            } else {   // EPI==2: scatter, guarded
                if (cm0) *(float2*)(C + (size_t)g_idx[rbase] * N + col)     = make_float2(v0, v1);
                if (cm1) *(float2*)(C + (size_t)g_idx[rbase + 8] * N + col) = make_float2(v2, v3);
            }
        }
    }
}

// ---------------- Stage 2: kv / ksum partials (compacted, dynamic bound) ----------------
#define KVROWS 32
__global__ __launch_bounds__(256)
void kv_partial_kernel()
{
    const int bh = blockIdx.x, chunk = blockIdx.y;
    const int b = bh / HH, h = bh % HH;

    int bound = g_npad[b] - chunk * CHUNK;
    if (bound <= 0) {   // zero partials so kv_final stays correct
        const int tid = threadIdx.x;
        float* out = g_kv_part + ((size_t)chunk * NBH + bh) * DH * DH;
        for (int i = tid; i < DH * DH; i += 256) out[i] = 0.0f;
        if (tid < DH) g_ksum_part[((size_t)chunk * NBH + bh) * DH + tid] = 0.0f;
        return;
    }
    if (bound > CHUNK) bound = CHUNK;
    const int NIT = bound / KVROWS;   // npad multiple of 128 -> exact

    const int tid = threadIdx.x;
    const int ty = tid >> 4, tx = tid & 15;

    __shared__ float ks[2][KVROWS][DH];
    __shared__ float vs[2][KVROWS][DH];

    const size_t rowbase = (size_t)b * LL + (size_t)chunk * CHUNK;
    const float* kptr = g_qkv + rowbase * N3D + DD     + h * DH;
    const float* vptr = g_qkv + rowbase * N3D + 2 * DD + h * DH;

    const uint32_t ksb = smem_u32(&ks[0][0][0]);
    const uint32_t vsb = smem_u32(&vs[0][0][0]);

    auto issue = [&](int buf, int l0) {
        #pragma unroll
        for (int i = 0; i < 2; i++) {
            int id  = tid + i * 256;
            int row = id >> 4, ch = id & 15;
            uint32_t so = (uint32_t)(buf * KVROWS * DH * 4 + row * DH * 4 + ch * 16);
            CP_ASYNC16(ksb + so, (const char*)(kptr + (size_t)(l0 + row) * N3D + ch * 4));
            CP_ASYNC16(vsb + so, (const char*)(vptr + (size_t)(l0 + row) * N3D + ch * 4));
        }
        CP_COMMIT();
    };

    float acc[4][4];
    #pragma unroll
    for (int i = 0; i < 4; i++)
        #pragma unroll
        for (int j = 0; j < 4; j++) acc[i][j] = 0.0f;
    float ksacc[4] = {0.f, 0.f, 0.f, 0.f};

    issue(0, 0);
    for (int it = 0; it < NIT; it++) {
        CP_WAIT(0);
        __syncthreads();
        if (it + 1 < NIT) issue((it + 1) & 1, (it + 1) * KVROWS);
        const int buf = it & 1;
        #pragma unroll 8
        for (int r = 0; r < KVROWS; r++) {
            float kr[4], vr[4];
            *(float4*)kr = *(const float4*)&ks[buf][r][ty * 4];
            *(float4*)vr = *(const float4*)&vs[buf][r][tx * 4];
            #pragma unroll
            for (int i = 0; i < 4; i++)
                #pragma unroll
                for (int j = 0; j < 4; j++)
                    acc[i][j] += kr[i] * vr[j];
            if (tx == 0) {
                #pragma unroll
                for (int i = 0; i < 4; i++) ksacc[i] += kr[i];
            }
        }
        __syncthreads();
    }

    float* out = g_kv_part + ((size_t)chunk * NBH + bh) * DH * DH;
    #pragma unroll
    for (int i = 0; i < 4; i++)
        #pragma unroll
        for (int j = 0; j < 4; j++)
            out[(ty * 4 + i) * DH + tx * 4 + j] = acc[i][j];
    if (tx == 0) {
        float* ko = g_ksum_part + ((size_t)chunk * NBH + bh) * DH;
        #pragma unroll
        for (int i = 0; i < 4; i++) ko[ty * 4 + i] = ksacc[i];
    }
}

__global__ void kv_final_kernel()
{
    const int bh = blockIdx.x;
    for (int idx = threadIdx.x; idx < DH * DH; idx += blockDim.x) {
        float s = 0.0f;
        #pragma unroll
        for (int c = 0; c < NCHUNK; c++)
            s += g_kv_part[((size_t)c * NBH + bh) * DH * DH + idx];
        g_kv[(size_t)bh * DH * DH + idx] = s;
    }
    for (int idx = threadIdx.x; idx < DH; idx += blockDim.x) {
        float s = 0.0f;
        #pragma unroll
        for (int c = 0; c < NCHUNK; c++)
            s += g_ksum_part[((size_t)c * NBH + bh) * DH + idx];
        g_ksum[(size_t)bh * DH + idx] = s;
    }
}

// ---------------- zq (compacted) ----------------
__global__ __launch_bounds__(256)
void zq_kernel()
{
    const int r = blockIdx.x;
    const int b = r >> 13;
    if ((r & (LL - 1)) >= g_npad[b]) return;

    __shared__ float qrow[DD];
    __shared__ float zs[HH];
    const int tid = threadIdx.x;
    const int wid = tid >> 5, lane = tid & 31;

    const float* qsrc = g_qkv + (size_t)r * N3D;
    ((float4*)qrow)[tid] = ((const float4*)qsrc)[tid];
    __syncthreads();

    #pragma unroll
    for (int hh = 2 * wid; hh < 2 * wid + 2; hh++) {
        const float* ks = g_ksum + ((size_t)b * HH + hh) * DH;
        float v = qrow[hh * DH + lane] * ks[lane]
                + qrow[hh * DH + 32 + lane] * ks[32 + lane];
        #pragma unroll
        for (int o = 16; o > 0; o >>= 1)
            v += __shfl_xor_sync(0xFFFFFFFF, v, o);
        if (lane == 0) zs[hh] = 1.0f / (v + 1e-6f);
    }
    __syncthreads();

    const int c = tid * 4;
    const float z = zs[c >> 6];
    union { __nv_bfloat16 b[4]; uint2 u; } H, L;
    #pragma unroll
    for (int j = 0; j < 4; j++) {
        float v = qrow[c + j] * z;
        __nv_bfloat16 h = __float2bfloat16(v);
        H.b[j] = h;
        L.b[j] = __float2bfloat16(v - __bfloat162float(h));
    }
    ((uint2*)(g_qphi + (size_t)r * DD))[tid] = H.u;
    ((uint2*)(g_qplo + (size_t)r * DD))[tid] = L.u;
}

// ---------------- M: M_T[b][n][h*64+d] = sum_m kv[b,h,d,m] * Wout[h*64+m, n] ----------------
__global__ __launch_bounds__(256)
void m_kernel(const float* __restrict__ Wout)
{
    __shared__ float kv_s[DH * 65];
    __shared__ float w_s[DH * 64];

    const int bh = blockIdx.x;
    const int b = bh >> 4, h = bh & 15;
    const int n0 = blockIdx.y * 64;
    const int tid = threadIdx.x;

    for (int i = tid; i < DH * DH; i += 256)
        kv_s[(i >> 6) * 65 + (i & 63)] = g_kv[(size_t)bh * DH * DH + i];
    for (int i = tid; i < DH * 64; i += 256) {
        int m = i >> 6, n = i & 63;
        w_s[m * 64 + n] = Wout[(size_t)(h * DH + m) * DD + n0 + n];
    }
    __syncthreads();

    const int d = tid & 63, ng = tid >> 6;
    float acc[16];
    #pragma unroll
    for (int j = 0; j < 16; j++) acc[j] = 0.0f;

    for (int m = 0; m < DH; m++) {
        const float kvd = kv_s[d * 65 + m];
        const float* wr = w_s + m * 64 + ng * 16;
        #pragma unroll
        for (int j = 0; j < 16; j += 4) {
            float4 w4 = *(const float4*)(wr + j);
            acc[j + 0] += kvd * w4.x;
            acc[j + 1] += kvd * w4.y;
            acc[j + 2] += kvd * w4.z;
            acc[j + 3] += kvd * w4.w;
        }
    }

    #pragma unroll
    for (int j = 0; j < 16; j++) {
        const int n = n0 + ng * 16 + j;
        const size_t o = ((size_t)b * DD + n) * DD + h * DH + d;
        float v = acc[j];
        __nv_bfloat16 hh = __float2bfloat16(v);
        g_mhi[o] = hh;
        g_mlo[o] = __float2bfloat16(v - __bfloat162float(hh));
    }
}

// ---------------- launch ----------------
extern "C" void kernel_launch(void* const* d_in, const int* in_sizes, int n_in,
                              void* d_out, int out_size)
{
    (void)in_sizes; (void)n_in; (void)out_size;
    const float* x    = (const float*)d_in[0];
    const int*   mask = (const int*)  d_in[1];
    const float* Wqkv = (const float*)d_in[2];
    const float* Wout = (const float*)d_in[3];
    float* out = (float*)d_out;

    __nv_bfloat16 *xhi, *xlo, *whi, *wlo, *qphi, *qplo, *mhi, *mlo;
    float *qkv_p;
    cudaGetSymbolAddress((void**)&xhi,  g_xhi);
    cudaGetSymbolAddress((void**)&xlo,  g_xlo);
    cudaGetSymbolAddress((void**)&whi,  g_whi);
    cudaGetSymbolAddress((void**)&wlo,  g_wlo);
    cudaGetSymbolAddress((void**)&qphi, g_qphi);
    cudaGetSymbolAddress((void**)&qplo, g_qplo);
    cudaGetSymbolAddress((void**)&mhi,  g_mhi);
    cudaGetSymbolAddress((void**)&mlo,  g_mlo);
    cudaGetSymbolAddress((void**)&qkv_p, g_qkv);

    cudaFuncSetAttribute(gemm_bf16_split<1>, cudaFuncAttributeMaxDynamicSharedMemorySize, SMEM_GEMM);
    cudaFuncSetAttribute(gemm_bf16_split<2>, cudaFuncAttributeMaxDynamicSharedMemorySize, SMEM_GEMM);

    // compaction + zero output
    scan_kernel<<<BB, 1024>>>(mask);
    zero_out<<<MM * DD / 4 / 256, 256>>>(out);

    // gather + split inputs
    conv_gather_x<<<MM, 256>>>(x);
    conv_wT<<<dim3(N3D / 32, DD / 32), dim3(32, 8)>>>(Wqkv, whi, wlo, DD, N3D);

    // G1: qkv = x_c @ Wqkv (compacted rows)
    gemm_bf16_split<1><<<dim3(N3D / 128, MM / 128), 256, SMEM_GEMM>>>(
        xhi, xlo, whi, wlo, qkv_p, N3D, DD);

    // S2: kv/ksum over compacted rows
    kv_partial_kernel<<<dim3(NBH, NCHUNK), 256>>>();
    kv_final_kernel<<<NBH, 256>>>();

    // z + q' = z*q
    zq_kernel<<<MM, 256>>>();

    // M_b^T
    m_kernel<<<dim3(NBH, DD / 64), 256>>>(Wout);

    // G2: out[g_idx] = q' @ M_b (scatter)
    gemm_bf16_split<2><<<dim3(DD / 128, MM / 128), 256, SMEM_GEMM>>>(
        qphi, qplo, mhi, mlo, out, DD, DD);
}